// round 13
// baseline (speedup 1.0000x reference)
#include <cuda_runtime.h>
#include <math.h>
#include <stdint.h>

typedef unsigned long long ull;

// ---------------- problem constants ----------------
#define NN 100000
#define EE 1600000
#define FD 125
#define PD 3
#define MSEL 131072            // pow2 >= NN
#define NBLK 128               // persistent blocks (all wave-1 resident)
#define NT (NBLK*256)          // grid threads = 32768
#define BB 128                 // speculative batch = NBLK
#define REGC 16384             // per-slot region capacity (slots > 0)
#define BMPW (1u<<24)          // 2^24 words = 2^30 bits bitmap (c <= 32768)
#define CMAXB 32768
#define QSCALE 17179869184.0   // 2^34 fixed-point scale
#define QINV   (1.0/17179869184.0)

// ---------------- static device scratch ----------------
__device__ double  g_sroot[NN];
__device__ double  g_srel[NN];
__device__ long long g_qrel[NN];
__device__ ull     g_relfix[NN];
__device__ int     g_deg[NN];
__device__ int     g_indptr[NN + 1];
__device__ int     g_fill[NN];
__device__ int     g_adj[NN + EE];
__device__ ull     g_key[MSEL];
__device__ int     g_cluster[NN];
__device__ int     g_centers[NN];
__device__ int     g_buggy[NN];
__device__ int     g_f0[NN];           // slot-0 region list (never truncates)
__device__ int     g_reg[BB][REGC];    // per-slot region lists (slots 1..BB-1)
__device__ int     g_regsz[BB];
__device__ unsigned g_mark[NN];        // speculative marks: (epoch<<10)|(1023-slot)
__device__ unsigned g_mark2[NN];       // verification visited tags
__device__ int     g_cand[BB];
__device__ int     g_candpos[BB];
__device__ int     g_unres[BB];        // slot unresolved (overflow/orphan/anomaly)
__device__ unsigned g_blkm[BB * 4];    // blocked-by bitmask per slot (from verify)
__device__ int     g_aflag[NT];
__device__ unsigned int g_enc[NN * FD];
__device__ ull     g_bmp[BMPW];        // 128MB
__device__ int     g_rowcnt[NN];
__device__ int     g_rowincl[NN];
__device__ int     g_aux[128];
__device__ int     g_selfcnt;
__device__ int     g_degmin;
__device__ int     g_depth;
__device__ int     g_c;
__device__ int     g_Etot;
// persistent-kernel coordination
__device__ int     g_epoch, g_P, g_C, g_found, g_selDone, g_scanbase;
__device__ int     g_barArrive, g_barGen;

// ---------------- init ----------------
__global__ void k_init() {
    int v = blockIdx.x * blockDim.x + threadIdx.x;
    if (v < NN) {
        g_deg[v] = 1;        // appended self-loop
        g_relfix[v] = 0ull;
        g_cluster[v] = -1;
        g_mark[v] = 0u;
        g_mark2[v] = 0u;
    }
    if (v < BB) { g_regsz[v] = 0; g_unres[v] = 0; }
    if (v < BB * 4) g_blkm[v] = 0u;
    if (v == 0) {
        g_selfcnt = 0; g_degmin = 0x7fffffff;
        g_epoch = 1; g_P = 0; g_C = 0;
        g_found = 0; g_scanbase = 0; g_selDone = 0;
        g_barArrive = 0; g_barGen = 0;
    }
}

// ---------------- per-node 128-dim dots (fp64, warp per node) ----------------
__global__ void k_dots(const float* __restrict__ x, const float* __restrict__ pos,
                       const float* __restrict__ wroot, const float* __restrict__ wrel) {
    int tid = threadIdx.x;
    int warp = tid >> 5, lane = tid & 31;
    int v = blockIdx.x * 8 + warp;
    if (v >= NN) return;
    double ar = 0.0, rr = 0.0;
    for (int d = lane; d < 128; d += 32) {
        double val = (d < FD) ? (double)x[(size_t)v * FD + d]
                              : (double)pos[(size_t)v * PD + (d - FD)];
        ar += val * (double)wroot[d];
        rr += val * (double)wrel[d];
    }
    for (int o = 16; o > 0; o >>= 1) {
        ar += __shfl_down_sync(0xffffffffu, ar, o);
        rr += __shfl_down_sync(0xffffffffu, rr, o);
    }
    if (lane == 0) {
        g_sroot[v] = ar;
        g_srel[v]  = rr;
        g_qrel[v]  = llrint(rr * QSCALE);
    }
}

// ---------------- edge pass ----------------
__global__ void k_edge1(const int* __restrict__ ei) {
    int e = blockIdx.x * blockDim.x + threadIdx.x;
    if (e >= EE) return;
    int s = ei[e], d = ei[EE + e];
    if (s == d) {
        atomicAdd(&g_selfcnt, 1);
    } else {
        atomicAdd(&g_deg[s], 1);
        atomicAdd(&g_relfix[d], (ull)g_qrel[s]);
    }
}

__global__ void k_minred() {
    int v = blockIdx.x * blockDim.x + threadIdx.x;
    if (v < NN) atomicMin(&g_degmin, g_deg[v]);
}

__global__ void k_kcalc() {
    long long kept = (long long)EE - g_selfcnt;
    double mean = (double)(kept + NN) / (double)NN;
    double b = log(mean - (double)g_degmin);
    double a = log(1.0 / 0.8);
    long long kk = (long long)ceil(a / b);
    int d = (int)kk + 2;
    if (d < 1) d = 1;
    if (d > 16) d = 16;
    g_depth = d;
}

// ---------------- score -> sortable key ----------------
__global__ void k_key(const float* __restrict__ bptr) {
    int i = blockIdx.x * blockDim.x + threadIdx.x;
    if (i >= MSEL) return;
    if (i < NN) {
        double sc = g_sroot[i] + g_srel[i] + (double)(long long)g_relfix[i] * QINV
                  + (double)bptr[0];
        float f = (float)sc;
        unsigned u = __float_as_uint(f);
        u = (u >> 31) ? ~u : (u | 0x80000000u);
        unsigned du = ~u;
        g_key[i] = ((ull)du << 32) | (unsigned)i;
    } else {
        g_key[i] = ~0ull;
    }
}

// ---------------- bitonic sort: global stage + smem-fused stages ----------------
__global__ void k_bitonic(int j, int k2) {
    int i = blockIdx.x * blockDim.x + threadIdx.x;
    int ixj = i ^ j;
    if (ixj > i) {
        ull a = g_key[i], b = g_key[ixj];
        bool up = ((i & k2) == 0);
        if ((a > b) == up) { g_key[i] = b; g_key[ixj] = a; }
    }
}

__global__ void __launch_bounds__(1024) k_sort_local() {
    __shared__ ull sh[2048];
    int base = blockIdx.x * 2048, t = threadIdx.x;
    sh[t] = g_key[base + t];
    sh[t + 1024] = g_key[base + t + 1024];
    __syncthreads();
    for (int k2 = 2; k2 <= 2048; k2 <<= 1) {
        for (int j = k2 >> 1; j > 0; j >>= 1) {
            #pragma unroll
            for (int q = 0; q < 2; q++) {
                int i = t + q * 1024;
                int ixj = i ^ j;
                if (ixj > i) {
                    bool up = (((base + i) & k2) == 0);
                    ull a = sh[i], b = sh[ixj];
                    if ((a > b) == up) { sh[i] = b; sh[ixj] = a; }
                }
            }
            __syncthreads();
        }
    }
    g_key[base + t] = sh[t];
    g_key[base + t + 1024] = sh[t + 1024];
}

__global__ void __launch_bounds__(1024) k_merge_local(int k2) {
    __shared__ ull sh[2048];
    int base = blockIdx.x * 2048, t = threadIdx.x;
    sh[t] = g_key[base + t];
    sh[t + 1024] = g_key[base + t + 1024];
    __syncthreads();
    for (int j = 1024; j > 0; j >>= 1) {
        #pragma unroll
        for (int q = 0; q < 2; q++) {
            int i = t + q * 1024;
            int ixj = i ^ j;
            if (ixj > i) {
                bool up = (((base + i) & k2) == 0);
                ull a = sh[i], b = sh[ixj];
                if ((a > b) == up) { sh[i] = b; sh[ixj] = a; }
            }
        }
        __syncthreads();
    }
    g_key[base + t] = sh[t];
    g_key[base + t + 1024] = sh[t + 1024];
}

// ---------------- scan A: deg -> indptr ----------------
__global__ void k_scanA1() {
    __shared__ int sh[1024];
    int b = blockIdx.x, tid = threadIdx.x;
    int idx = b * 1024 + tid;
    int v = (idx < NN) ? g_deg[idx] : 0;
    sh[tid] = v;
    __syncthreads();
    for (int d = 1; d < 1024; d <<= 1) {
        int t = (tid >= d) ? sh[tid - d] : 0;
        __syncthreads();
        sh[tid] += t;
        __syncthreads();
    }
    if (idx < NN) g_indptr[idx + 1] = sh[tid];
    if (tid == 1023) g_aux[b] = sh[1023];
}
__global__ void k_scanA2() {
    int run = 0;
    for (int b = 0; b < 98; b++) { int t = g_aux[b]; g_aux[b] = run; run += t; }
    g_indptr[0] = 0;
}
__global__ void k_scanA3() {
    int idx = blockIdx.x * 1024 + threadIdx.x;
    if (idx < NN) g_indptr[idx + 1] += g_aux[idx >> 10];
}

__global__ void k_fillself() {
    int v = blockIdx.x * 1024 + threadIdx.x;
    if (v < NN) {
        int p = g_indptr[v];
        g_adj[p] = v;          // self-loop at slot 0
        g_fill[v] = p + 1;
    }
}
__global__ void k_adjE(const int* __restrict__ ei) {
    int e = blockIdx.x * blockDim.x + threadIdx.x;
    if (e >= EE) return;
    int s = ei[e], d = ei[EE + e];
    if (s != d) g_adj[atomicAdd(&g_fill[s], 1)] = d;
}

// ---------------- grid barrier (all NBLK blocks resident) ----------------
__device__ __forceinline__ void gridbar(int* sgen) {
    __syncthreads();
    if (threadIdx.x == 0) {
        int g = *sgen;
        __threadfence();
        if (atomicAdd(&g_barArrive, 1) == NBLK - 1) {
            atomicExch(&g_barArrive, 0);
            __threadfence();
            atomicAdd(&g_barGen, 1);
        } else {
            while (atomicAdd(&g_barGen, 0) < g + 1) { }
        }
        __threadfence();
        *sgen = g + 1;
    }
    __syncthreads();
}

// ------- speculative peel v6: no HARD aborts; post-hoc verification BFS -------
__global__ void __launch_bounds__(256) k_peel6() {
    __shared__ int s_gen, s_abort, s_unres, s_hi, s_sz1, s_cnt, s_stop, s_ncommit;
    __shared__ int s_pref[256];
    __shared__ unsigned s_myB[4];     // own blocked-by mask (verify phase)
    __shared__ int s_ms[BB];
    __shared__ int s_unresArr[BB];
    __shared__ unsigned s_B[BB * 4];
    __shared__ int s_cls[BB];
    __shared__ int s_rank[BB];
    int tid = threadIdx.x;
    int blk = blockIdx.x;
    if (tid == 0) s_gen = g_barGen;
    __syncthreads();
    int depth = g_depth;

    for (int round = 0; round < NN; round++) {
        // ---- candidate selection: first BB alive in sel order from g_P ----
        while (true) {
            int scanb = g_scanbase;
            int tg = blk * 256 + tid;
            int pos = scanb + tg;
            int fl = 0;
            if (pos < NN) {
                int s = (int)(g_key[pos] & 0xffffffffu);
                if (g_cluster[s] == -1) fl = 1;
            }
            g_aflag[tg] = fl;
            gridbar(&s_gen);                                   // bar 1
            if (blk == 0) {
                int found0 = g_found;
                int need = BB - found0;
                const int FPT = NT / 256;                      // 128 flags/thread
                int base = tid * FPT;
                int cnt = 0;
                for (int k2 = 0; k2 < FPT; k2++) cnt += g_aflag[base + k2];
                s_pref[tid] = cnt;
                __syncthreads();
                for (int d = 1; d < 256; d <<= 1) {
                    int v = (tid >= d) ? s_pref[tid - d] : 0;
                    __syncthreads();
                    s_pref[tid] += v;
                    __syncthreads();
                }
                int excl = s_pref[tid] - cnt;
                int total = s_pref[255];
                int r = excl;
                for (int k2 = 0; k2 < FPT; k2++) {
                    if (g_aflag[base + k2]) {
                        if (r < need) {
                            int p2 = scanb + base + k2;
                            g_cand[found0 + r] = (int)(g_key[p2] & 0xffffffffu);
                            g_candpos[found0 + r] = p2;
                        }
                        r++;
                    }
                }
                __syncthreads();
                if (tid == 0) {
                    int add = total < need ? total : need;
                    int nf = found0 + add;
                    int nsb = scanb + NT;
                    g_found = nf;
                    g_scanbase = nsb;
                    g_selDone = (nf >= BB || nsb >= NN) ? 1 : 0;
                }
            }
            gridbar(&s_gen);                                   // bar 2
            if (g_selDone) break;
        }

        int found = g_found;
        int epoch = g_epoch;
        if (found == 0) break;

        // ---- phase 1: greedy speculative BFS (no aborts on steal) ----
        int slot = blk;
        int* reg = (slot == 0) ? g_f0 : g_reg[slot];
        int cap  = (slot == 0) ? NN : REGC;
        int center = (blk < found) ? g_cand[slot] : 0;
        unsigned mykey = ((unsigned)epoch << 10) | (unsigned)(1023 - slot);
        if (blk < found) {
            if (tid == 0) {
                s_abort = 0; s_unres = 0; s_hi = 0;
                unsigned old = atomicMax(&g_mark[center], mykey);
                int lost = 0;
                if ((old >> 10) == (unsigned)epoch) {
                    int os = 1023 - (int)(old & 1023u);
                    if (os < slot) lost = 1;    // center captured: dead candidate
                }
                if (!lost) { reg[0] = center; s_hi = 1; }
                else s_abort = 1;
            }
            __syncthreads();
            int lo = 0;
            for (int lev = 0; lev < depth; lev++) {
                if (s_abort) break;
                int hi = s_hi; if (hi > cap) hi = cap;
                if (hi == lo) break;
                // late-kill poll: a smaller slot captured our center
                if (tid == 0 && g_mark[center] != mykey) s_abort = 1;
                __syncthreads();
                if (s_abort) break;
                for (int i = lo + tid; i < hi; i += 256) {
                    int u = reg[i];
                    int e0 = g_indptr[u] + 1, e1 = g_indptr[u + 1];  // skip self slot
                    for (int e = e0; e < e1; e++) {
                        int w = g_adj[e];
                        if (g_cluster[w] != -1) continue;
                        unsigned old = atomicMax(&g_mark[w], mykey);
                        bool own;
                        if ((old >> 10) != (unsigned)epoch) own = true;
                        else {
                            int os = 1023 - (int)(old & 1023u);
                            if (os == slot) continue;
                            if (os < slot) continue;   // lost at touch: fine
                            own = true;                // stole from bigger slot
                        }
                        if (own) {
                            int j = atomicAdd(&s_hi, 1);
                            if (j < cap) reg[j] = w;
                            else { s_unres = 1; s_abort = 1; }
                        }
                    }
                }
                __syncthreads();
                lo = hi;
            }
            __syncthreads();
            if (tid == 0) s_sz1 = s_hi < cap ? s_hi : cap;
        }
        gridbar(&s_gen);                                       // bar 3

        // ---- phase 2: verification re-BFS over final marks ----
        if (blk < found) {
            if (tid < 4) s_myB[tid] = 0u;
            if (tid == 0) s_cnt = 0;
            __syncthreads();
            unsigned cm = g_mark[center];
            int doverify = (cm == mykey) && !s_unres;
            if (doverify) {
                int sz1 = s_sz1;
                int local = 0;
                for (int i = tid; i < sz1; i += 256)
                    if (g_mark[reg[i]] == mykey) local++;
                atomicAdd(&s_cnt, local);
                __syncthreads();
                int cntm = s_cnt;
                if (tid == 0) { g_mark2[center] = mykey; reg[0] = center; s_hi = 1; }
                __syncthreads();
                int lo = 0;
                for (int lev = 0; lev < depth; lev++) {
                    int hi = s_hi; if (hi > cap) hi = cap;
                    if (hi == lo) break;
                    for (int i = lo + tid; i < hi; i += 256) {
                        int u = reg[i];
                        int e0 = g_indptr[u] + 1, e1 = g_indptr[u + 1];
                        for (int e = e0; e < e1; e++) {
                            int w = g_adj[e];
                            if (g_cluster[w] != -1) continue;
                            unsigned m = g_mark[w];
                            if (m == mykey) {
                                unsigned o2 = atomicExch(&g_mark2[w], mykey);
                                if (o2 != mykey) {
                                    int j = atomicAdd(&s_hi, 1);
                                    if (j < cap) reg[j] = w;
                                    else s_unres = 1;
                                }
                            } else if ((m >> 10) == (unsigned)epoch) {
                                int os = 1023 - (int)(m & 1023u);
                                if (os < slot)
                                    atomicOr(&s_myB[os >> 5], 1u << (os & 31));
                                else s_unres = 1;   // anomaly: conservative
                            } else s_unres = 1;     // anomaly: conservative
                        }
                    }
                    __syncthreads();
                    lo = hi;
                }
                __syncthreads();
                if (tid == 0) {
                    int rsz = s_hi < cap ? s_hi : cap;
                    if (s_hi != cntm) s_unres = 1;   // orphaned / detoured region
                    g_regsz[slot] = rsz;
                }
            } else {
                if (tid == 0) g_regsz[slot] = 0;
            }
            __syncthreads();
            if (tid < 4) g_blkm[slot * 4 + tid] = s_myB[tid];
            if (tid == 0) g_unres[slot] = (cm == mykey) ? s_unres : 0;
        }
        gridbar(&s_gen);                                       // bar 4

        // ---- commit analysis (redundant per block): prefetch, serial walk ----
        for (int s = tid; s < found; s += 256) {
            unsigned m = g_mark[g_cand[s]];
            int ms = -1;
            if ((m >> 10) == (unsigned)epoch) ms = 1023 - (int)(m & 1023u);
            s_ms[s] = ms;
            s_unresArr[s] = g_unres[s];
        }
        for (int i = tid; i < found * 4; i += 256) s_B[i] = g_blkm[i];
        __syncthreads();
        if (tid == 0) {
            unsigned ex0 = 0, ex1 = 0, ex2 = 0, ex3 = 0;
            int stop = found, r = 0;
            for (int s = 0; s < found; s++) {
                int ms = s_ms[s];
                if (ms == s && !s_unresArr[s]) {
                    bool ok = ((s_B[4*s+0] & ~ex0) == 0) && ((s_B[4*s+1] & ~ex1) == 0)
                           && ((s_B[4*s+2] & ~ex2) == 0) && ((s_B[4*s+3] & ~ex3) == 0);
                    if (ok) {
                        s_cls[s] = 1; s_rank[s] = r; r++;
                        if      (s < 32)  ex0 |= 1u << s;
                        else if (s < 64)  ex1 |= 1u << (s - 32);
                        else if (s < 96)  ex2 |= 1u << (s - 64);
                        else              ex3 |= 1u << (s - 96);
                    } else { stop = s; break; }
                } else if (ms >= 0 && ms < s &&
                           (((ms < 32 ? ex0 : ms < 64 ? ex1 : ms < 96 ? ex2 : ex3)
                             >> (ms & 31)) & 1u)) {
                    s_cls[s] = 0;                 // dead: center in exact region
                } else { stop = s; break; }
            }
            s_stop = stop; s_ncommit = r;
        }
        __syncthreads();
        int stop = s_stop;                        // >= 1 (slot 0 always exact)
        int C = g_C;

        // committed slots write their verified regions with re-ranked ids
        if (blk < stop && s_cls[blk] == 1) {
            int sz = g_regsz[blk];
            int cid = C + s_rank[blk];
            for (int i = tid; i < sz; i += 256) g_cluster[reg[i]] = cid;
        }
        if (blk == 0) {
            for (int s = tid; s < stop; s += 256)
                if (s_cls[s] == 1) g_centers[C + s_rank[s]] = g_cand[s];
            if (tid == 0) {
                g_C = C + s_ncommit;
                int np = g_candpos[stop - 1] + 1;
                g_P = np;
                g_epoch = epoch + 1;
                g_found = 0; g_scanbase = np; g_selDone = 0;
            }
        }
        gridbar(&s_gen);                                       // bar 5
    }
    if (blk == 0 && tid == 0) g_c = g_C;
}

// ---------------- concat reconstruction: key = (cluster<<32 | node) ----------------
__global__ void k_key2() {
    int i = blockIdx.x * blockDim.x + threadIdx.x;
    if (i >= MSEL) return;
    if (i < NN) {
        int cl = g_cluster[i];
        unsigned uc = (cl < 0) ? 0x7fffffffu : (unsigned)cl;
        g_key[i] = ((ull)uc << 32) | (unsigned)i;
    } else {
        g_key[i] = ~0ull;
    }
}

// After sort: position p holds key[p] = (cid[p]<<32 | oid[p]).
// Reference: clusters_buggy[v] = cid[ oid[v] ]  (cluster-id AT POSITION oid[v]).
__global__ void k_buggy() {
    int v = blockIdx.x * blockDim.x + threadIdx.x;
    if (v >= NN) return;
    int p = (int)(g_key[v] & 0xffffffffu);   // oid[v]
    int cid = 0;
    if (p >= 0 && p < NN) cid = (int)(g_key[p] >> 32);
    g_buggy[v] = cid;
}

// ---------------- edge dedup bitmap ----------------
__global__ void k_clearbmp() {
    int c = g_c; if (c > CMAXB) c = CMAXB;
    long long cw = (c + 63) >> 6;
    long long nw = (long long)c * cw;
    if (nw > (long long)BMPW) nw = BMPW;
    long long stride = (long long)gridDim.x * blockDim.x;
    for (long long i = blockIdx.x * (long long)blockDim.x + threadIdx.x; i < nw; i += stride)
        g_bmp[i] = 0ull;
}
__global__ void k_mark(const int* __restrict__ ei) {
    int e = blockIdx.x * blockDim.x + threadIdx.x;
    if (e >= EE) return;
    int s = ei[e], d = ei[EE + e];
    if (s == d) return;
    int a = g_buggy[s], b = g_buggy[d];
    if (a == b) return;
    int c = g_c;
    if (c > CMAXB) return;
    long long cw = (c + 63) >> 6;
    if (a < 0 || a >= c || b < 0 || b >= c) return;
    long long bit = (long long)a * (cw << 6) + b;
    atomicOr(&g_bmp[bit >> 6], 1ull << (bit & 63));
}
__global__ void k_rowcnt() {
    int a = blockIdx.x * blockDim.x + threadIdx.x;
    int c = g_c;
    if (a >= NN) return;
    if (a >= c || c > CMAXB) { g_rowcnt[a] = 0; return; }
    long long cw = (c + 63) >> 6;
    int cnt = 0;
    for (long long w = 0; w < cw; w++) cnt += __popcll(g_bmp[(long long)a * cw + w]);
    g_rowcnt[a] = cnt;
}

// ---------------- scan B ----------------
__global__ void k_scanB1() {
    __shared__ int sh[1024];
    int n = g_c; if (n > NN) n = NN;
    int b = blockIdx.x, tid = threadIdx.x;
    int idx = b * 1024 + tid;
    int v = (idx < n) ? g_rowcnt[idx] : 0;
    sh[tid] = v;
    __syncthreads();
    for (int d = 1; d < 1024; d <<= 1) {
        int t = (tid >= d) ? sh[tid - d] : 0;
        __syncthreads();
        sh[tid] += t;
        __syncthreads();
    }
    if (idx < n) g_rowincl[idx] = sh[tid];
    if (tid == 1023) g_aux[b] = sh[1023];
}
__global__ void k_scanB2() {
    int run = 0;
    for (int b = 0; b < 98; b++) { int t = g_aux[b]; g_aux[b] = run; run += t; }
}
__global__ void k_scanB3() {
    int n = g_c; if (n > NN) n = NN;
    int idx = blockIdx.x * 1024 + threadIdx.x;
    if (idx < n) g_rowincl[idx] += g_aux[idx >> 10];
}
__global__ void k_setE() {
    int c = g_c;
    g_Etot = (c > 0 && c <= NN) ? g_rowincl[c - 1] : 0;
}

// ---------------- x_p = segment_max ----------------
__global__ void k_xclear() {
    long long i = blockIdx.x * (long long)blockDim.x + threadIdx.x;
    if (i < (long long)NN * FD) g_enc[i] = 0u;
}
__global__ void k_xmax(const float* __restrict__ x) {
    long long i = blockIdx.x * (long long)blockDim.x + threadIdx.x;
    if (i >= (long long)NN * FD) return;
    int v = (int)(i / FD), f = (int)(i % FD);
    int cl = g_cluster[v];
    if (cl < 0 || cl >= NN) return;
    unsigned u = __float_as_uint(x[i]);
    u = (u >> 31) ? ~u : (u | 0x80000000u);
    atomicMax(&g_enc[(long long)cl * FD + f], u);
}
__global__ void k_xout(float* __restrict__ out, long long osz) {
    long long i = blockIdx.x * (long long)blockDim.x + threadIdx.x;
    if (i >= (long long)g_c * FD || i >= osz) return;
    unsigned u = g_enc[i];
    unsigned bits = (u & 0x80000000u) ? (u ^ 0x80000000u) : ~u;
    out[i] = __uint_as_float(bits);
}

// ---------------- new_ei emission ----------------
__global__ void k_emit(float* __restrict__ out, long long osz) {
    int a = blockIdx.x * blockDim.x + threadIdx.x;
    int c = g_c;
    if (a >= c || c > CMAXB) return;
    long long cw = (c + 63) >> 6;
    int base = g_rowincl[a] - g_rowcnt[a];
    long long eoff = (long long)FD * c;
    int Et = g_Etot;
    int cnt = 0;
    for (long long w = 0; w < cw; w++) {
        ull u = g_bmp[(long long)a * cw + w];
        while (u) {
            int bpos = __ffsll((long long)u) - 1;
            int b = (int)(w * 64 + bpos);
            long long p0 = eoff + base + cnt;
            long long p1 = eoff + Et + base + cnt;
            if (p0 >= 0 && p0 < osz) out[p0] = (float)a;
            if (p1 >= 0 && p1 < osz) out[p1] = (float)b;
            cnt++;
            u &= (u - 1);
        }
    }
}

// ---------------- pos_p ----------------
__global__ void k_posout(const float* __restrict__ pos, float* __restrict__ out,
                         long long osz) {
    int i = blockIdx.x * blockDim.x + threadIdx.x;
    int c = g_c;
    if (i >= 3 * c) return;
    int j = i / 3, d = i % 3;
    int ctr = g_centers[j];
    if (ctr < 0 || ctr >= NN) return;
    long long off = (long long)FD * c + 2LL * g_Etot + i;
    if (off >= 0 && off < osz)
        out[off] = pos[(long long)ctr * 3 + d];
}

// ---------------- host-side sort driver (launches only) ----------------
static void run_sort() {
    k_sort_local<<<MSEL / 2048, 1024>>>();
    for (int k2 = 4096; k2 <= MSEL; k2 <<= 1) {
        for (int j = k2 >> 1; j >= 2048; j >>= 1)
            k_bitonic<<<MSEL / 256, 256>>>(j, k2);
        k_merge_local<<<MSEL / 2048, 1024>>>(k2);
    }
}

// ---------------- launch ----------------
extern "C" void kernel_launch(void* const* d_in, const int* in_sizes, int n_in,
                              void* d_out, int out_size) {
    const float* x     = (const float*)d_in[0];
    const int*   ei    = (const int*)d_in[1];
    const float* pos   = (const float*)d_in[2];
    const float* wroot = (const float*)d_in[3];
    const float* wrel  = (const float*)d_in[4];
    const float* bb    = (const float*)d_in[5];
    float* out = (float*)d_out;
    long long osz = (long long)out_size;

    k_init<<<(NN + 255) / 256, 256>>>();
    k_dots<<<(NN + 7) / 8, 256>>>(x, pos, wroot, wrel);
    k_edge1<<<(EE + 255) / 256, 256>>>(ei);
    k_minred<<<(NN + 255) / 256, 256>>>();
    k_kcalc<<<1, 1>>>();
    k_key<<<MSEL / 256, 256>>>(bb);
    run_sort();                                   // sel order
    k_scanA1<<<98, 1024>>>();
    k_scanA2<<<1, 1>>>();
    k_scanA3<<<98, 1024>>>();
    k_fillself<<<98, 1024>>>();
    k_adjE<<<(EE + 255) / 256, 256>>>(ei);
    k_peel6<<<NBLK, 256>>>();
    k_key2<<<MSEL / 256, 256>>>();
    run_sort();                                   // concat order (cluster, node)
    k_clearbmp<<<2048, 256>>>();
    k_buggy<<<(NN + 255) / 256, 256>>>();
    k_mark<<<(EE + 255) / 256, 256>>>(ei);
    k_rowcnt<<<(NN + 255) / 256, 256>>>();
    k_scanB1<<<98, 1024>>>();
    k_scanB2<<<1, 1>>>();
    k_scanB3<<<98, 1024>>>();
    k_setE<<<1, 1>>>();
    k_xclear<<<(NN * FD + 255) / 256, 256>>>();
    k_xmax<<<(NN * FD + 255) / 256, 256>>>(x);
    k_xout<<<(NN * FD + 255) / 256, 256>>>(out, osz);
    k_emit<<<(NN + 255) / 256, 256>>>(out, osz);
    k_posout<<<(3 * NN + 255) / 256, 256>>>(pos, out, osz);
}

// round 14
// speedup vs baseline: 1.0504x; 1.0504x over previous
#include <cuda_runtime.h>
#include <math.h>
#include <stdint.h>

typedef unsigned long long ull;

// ---------------- problem constants ----------------
#define NN 100000
#define EE 1600000
#define FD 125
#define PD 3
#define MSEL 131072            // pow2 >= NN
#define NBLK 128               // persistent blocks (all wave-1 resident)
#define NT (NBLK*256)          // grid threads = 32768
#define BB 128                 // speculative batch = NBLK
#define REGC 16384             // per-slot region capacity (slots > 0)
#define BMPW (1u<<24)          // 2^24 words = 2^30 bits bitmap (c <= 32768)
#define CMAXB 32768
#define QSCALE 17179869184.0   // 2^34 fixed-point scale
#define QINV   (1.0/17179869184.0)

// ---------------- static device scratch ----------------
__device__ double  g_sroot[NN];
__device__ double  g_srel[NN];
__device__ long long g_qrel[NN];
__device__ ull     g_relfix[NN];
__device__ int     g_deg[NN];
__device__ int     g_indptr[NN + 1];
__device__ int     g_fill[NN];
__device__ int     g_adj[NN + EE];
__device__ ull     g_key[MSEL];
__device__ int     g_cluster[NN];
__device__ int     g_centers[NN];
__device__ int     g_buggy[NN];
__device__ int     g_f0[NN];           // slot-0 region list (never truncates)
__device__ int     g_reg[BB][REGC];    // per-slot region lists (slots 1..BB-1)
__device__ int     g_regsz[BB];
__device__ unsigned g_mark[NN];        // speculative marks: (epoch<<10)|(1023-slot)
__device__ int     g_cand[BB];
__device__ int     g_candpos[BB];
__device__ int     g_conf[2][BB];      // HARD flags, double-buffered by round parity
__device__ unsigned g_blkm[BB * 4];    // blocked-by bitmask (lost-at-touch), per slot
__device__ int     g_aflag[NT];
__device__ unsigned int g_enc[NN * FD];
__device__ ull     g_bmp[BMPW];        // 128MB
__device__ int     g_rowcnt[NN];
__device__ int     g_rowincl[NN];
__device__ int     g_aux[128];
__device__ int     g_selfcnt;
__device__ int     g_degmin;
__device__ int     g_depth;
__device__ int     g_c;
__device__ int     g_Etot;
// persistent-kernel coordination
__device__ int     g_epoch, g_C, g_qn, g_needtop, g_scanbase;
__device__ int     g_barArrive, g_barGen;

// ---------------- init ----------------
__global__ void k_init() {
    int v = blockIdx.x * blockDim.x + threadIdx.x;
    if (v < NN) {
        g_deg[v] = 1;        // appended self-loop
        g_relfix[v] = 0ull;
        g_cluster[v] = -1;
        g_mark[v] = 0u;
    }
    if (v < BB) { g_conf[0][v] = 0; g_conf[1][v] = 0; g_regsz[v] = 0; }
    if (v < BB * 4) g_blkm[v] = 0u;
    if (v == 0) {
        g_selfcnt = 0; g_degmin = 0x7fffffff;
        g_epoch = 1; g_C = 0;
        g_qn = 0; g_needtop = 0; g_scanbase = 0;
        g_barArrive = 0; g_barGen = 0;
    }
}

// ---------------- per-node 128-dim dots (fp64, warp per node) ----------------
__global__ void k_dots(const float* __restrict__ x, const float* __restrict__ pos,
                       const float* __restrict__ wroot, const float* __restrict__ wrel) {
    int tid = threadIdx.x;
    int warp = tid >> 5, lane = tid & 31;
    int v = blockIdx.x * 8 + warp;
    if (v >= NN) return;
    double ar = 0.0, rr = 0.0;
    for (int d = lane; d < 128; d += 32) {
        double val = (d < FD) ? (double)x[(size_t)v * FD + d]
                              : (double)pos[(size_t)v * PD + (d - FD)];
        ar += val * (double)wroot[d];
        rr += val * (double)wrel[d];
    }
    for (int o = 16; o > 0; o >>= 1) {
        ar += __shfl_down_sync(0xffffffffu, ar, o);
        rr += __shfl_down_sync(0xffffffffu, rr, o);
    }
    if (lane == 0) {
        g_sroot[v] = ar;
        g_srel[v]  = rr;
        g_qrel[v]  = llrint(rr * QSCALE);
    }
}

// ---------------- edge pass ----------------
__global__ void k_edge1(const int* __restrict__ ei) {
    int e = blockIdx.x * blockDim.x + threadIdx.x;
    if (e >= EE) return;
    int s = ei[e], d = ei[EE + e];
    if (s == d) {
        atomicAdd(&g_selfcnt, 1);
    } else {
        atomicAdd(&g_deg[s], 1);
        atomicAdd(&g_relfix[d], (ull)g_qrel[s]);
    }
}

__global__ void k_minred() {
    int v = blockIdx.x * blockDim.x + threadIdx.x;
    if (v < NN) atomicMin(&g_degmin, g_deg[v]);
}

__global__ void k_kcalc() {
    long long kept = (long long)EE - g_selfcnt;
    double mean = (double)(kept + NN) / (double)NN;
    double b = log(mean - (double)g_degmin);
    double a = log(1.0 / 0.8);
    long long kk = (long long)ceil(a / b);
    int d = (int)kk + 2;
    if (d < 1) d = 1;
    if (d > 16) d = 16;
    g_depth = d;
}

// ---------------- score -> sortable key ----------------
__global__ void k_key(const float* __restrict__ bptr) {
    int i = blockIdx.x * blockDim.x + threadIdx.x;
    if (i >= MSEL) return;
    if (i < NN) {
        double sc = g_sroot[i] + g_srel[i] + (double)(long long)g_relfix[i] * QINV
                  + (double)bptr[0];
        float f = (float)sc;
        unsigned u = __float_as_uint(f);
        u = (u >> 31) ? ~u : (u | 0x80000000u);
        unsigned du = ~u;
        g_key[i] = ((ull)du << 32) | (unsigned)i;
    } else {
        g_key[i] = ~0ull;
    }
}

// ---------------- bitonic sort: global stage + smem-fused stages ----------------
__global__ void k_bitonic(int j, int k2) {
    int i = blockIdx.x * blockDim.x + threadIdx.x;
    int ixj = i ^ j;
    if (ixj > i) {
        ull a = g_key[i], b = g_key[ixj];
        bool up = ((i & k2) == 0);
        if ((a > b) == up) { g_key[i] = b; g_key[ixj] = a; }
    }
}

__global__ void __launch_bounds__(1024) k_sort_local() {
    __shared__ ull sh[2048];
    int base = blockIdx.x * 2048, t = threadIdx.x;
    sh[t] = g_key[base + t];
    sh[t + 1024] = g_key[base + t + 1024];
    __syncthreads();
    for (int k2 = 2; k2 <= 2048; k2 <<= 1) {
        for (int j = k2 >> 1; j > 0; j >>= 1) {
            #pragma unroll
            for (int q = 0; q < 2; q++) {
                int i = t + q * 1024;
                int ixj = i ^ j;
                if (ixj > i) {
                    bool up = (((base + i) & k2) == 0);
                    ull a = sh[i], b = sh[ixj];
                    if ((a > b) == up) { sh[i] = b; sh[ixj] = a; }
                }
            }
            __syncthreads();
        }
    }
    g_key[base + t] = sh[t];
    g_key[base + t + 1024] = sh[t + 1024];
}

__global__ void __launch_bounds__(1024) k_merge_local(int k2) {
    __shared__ ull sh[2048];
    int base = blockIdx.x * 2048, t = threadIdx.x;
    sh[t] = g_key[base + t];
    sh[t + 1024] = g_key[base + t + 1024];
    __syncthreads();
    for (int j = 1024; j > 0; j >>= 1) {
        #pragma unroll
        for (int q = 0; q < 2; q++) {
            int i = t + q * 1024;
            int ixj = i ^ j;
            if (ixj > i) {
                bool up = (((base + i) & k2) == 0);
                ull a = sh[i], b = sh[ixj];
                if ((a > b) == up) { sh[i] = b; sh[ixj] = a; }
            }
        }
        __syncthreads();
    }
    g_key[base + t] = sh[t];
    g_key[base + t + 1024] = sh[t + 1024];
}

// ---------------- scan A: deg -> indptr ----------------
__global__ void k_scanA1() {
    __shared__ int sh[1024];
    int b = blockIdx.x, tid = threadIdx.x;
    int idx = b * 1024 + tid;
    int v = (idx < NN) ? g_deg[idx] : 0;
    sh[tid] = v;
    __syncthreads();
    for (int d = 1; d < 1024; d <<= 1) {
        int t = (tid >= d) ? sh[tid - d] : 0;
        __syncthreads();
        sh[tid] += t;
        __syncthreads();
    }
    if (idx < NN) g_indptr[idx + 1] = sh[tid];
    if (tid == 1023) g_aux[b] = sh[1023];
}
__global__ void k_scanA2() {
    int run = 0;
    for (int b = 0; b < 98; b++) { int t = g_aux[b]; g_aux[b] = run; run += t; }
    g_indptr[0] = 0;
}
__global__ void k_scanA3() {
    int idx = blockIdx.x * 1024 + threadIdx.x;
    if (idx < NN) g_indptr[idx + 1] += g_aux[idx >> 10];
}

__global__ void k_fillself() {
    int v = blockIdx.x * 1024 + threadIdx.x;
    if (v < NN) {
        int p = g_indptr[v];
        g_adj[p] = v;          // self-loop at slot 0
        g_fill[v] = p + 1;
    }
}
__global__ void k_adjE(const int* __restrict__ ei) {
    int e = blockIdx.x * blockDim.x + threadIdx.x;
    if (e >= EE) return;
    int s = ei[e], d = ei[EE + e];
    if (s != d) g_adj[atomicAdd(&g_fill[s], 1)] = d;
}

// -------- grid barrier (all NBLK blocks resident; volatile poll + backoff) --------
__device__ __forceinline__ void gridbar(int* sgen) {
    __syncthreads();
    if (threadIdx.x == 0) {
        int g = *sgen;
        __threadfence();
        if (atomicAdd(&g_barArrive, 1) == NBLK - 1) {
            atomicExch(&g_barArrive, 0);
            __threadfence();
            atomicAdd(&g_barGen, 1);
        } else {
            while (((volatile int*)&g_barGen)[0] < g + 1) __nanosleep(64);
        }
        __threadfence();
        *sgen = g + 1;
    }
    __syncthreads();
}

// ------- speculative peel v7: v5 logic + cached candidate queue, 3 bars/round -------
__global__ void __launch_bounds__(256) k_peel7() {
    __shared__ int s_gen, s_abort, s_hi, s_stop, s_ncommit, s_lastp;
    __shared__ int s_pref[256];
    __shared__ int s_alive[BB];
    __shared__ int s_ms[BB];
    __shared__ int s_flag[BB];
    __shared__ unsigned s_B[BB * 4];
    __shared__ int s_cls[BB];
    __shared__ int s_rank[BB];
    int tid = threadIdx.x;
    int blk = blockIdx.x;
    if (tid == 0) s_gen = g_barGen;
    __syncthreads();
    int depth = g_depth;

    for (int round = 0; round < NN; round++) {
        int par = round & 1;
        // clear next round's HARD flag buffer + own soft-block mask.
        // Safe: last reads of both were before the previous round's closing bar.
        if (tid == 0) g_conf[par ^ 1][blk] = 0;
        if (tid < 4) g_blkm[blk * 4 + tid] = 0u;

        // ---- queue compaction (block 0): drop claimed candidates, keep order ----
        if (blk == 0) {
            int qn = g_qn;
            for (int i = tid; i < qn; i += 256)
                s_alive[i] = (g_cluster[g_cand[i]] == -1) ? 1 : 0;
            __syncthreads();
            if (tid == 0) {
                int w = 0;
                for (int i = 0; i < qn; i++) {
                    if (s_alive[i]) {
                        if (w != i) { g_cand[w] = g_cand[i]; g_candpos[w] = g_candpos[i]; }
                        w++;
                    }
                }
                g_qn = w;
                g_needtop = (w < BB && g_scanbase < NN) ? 1 : 0;
            }
        }
        gridbar(&s_gen);                                       // bar 1

        // ---- top-up scan (rare): append next alive in sel order ----
        while (g_needtop) {
            int scanb = g_scanbase;
            int tg = blk * 256 + tid;
            int pos = scanb + tg;
            int fl = 0;
            if (pos < NN) {
                int s = (int)(g_key[pos] & 0xffffffffu);
                if (g_cluster[s] == -1) fl = 1;
            }
            g_aflag[tg] = fl;
            gridbar(&s_gen);                                   // scan bar a
            if (blk == 0) {
                int qn = g_qn;
                int need = BB - qn;
                const int FPT = NT / 256;                      // 128 flags/thread
                int base = tid * FPT;
                int cnt = 0;
                for (int k2 = 0; k2 < FPT; k2++) cnt += g_aflag[base + k2];
                s_pref[tid] = cnt;
                __syncthreads();
                for (int d = 1; d < 256; d <<= 1) {
                    int v = (tid >= d) ? s_pref[tid - d] : 0;
                    __syncthreads();
                    s_pref[tid] += v;
                    __syncthreads();
                }
                int excl = s_pref[tid] - cnt;
                int total = s_pref[255];
                int add = total < need ? total : need;
                int r = excl;
                for (int k2 = 0; k2 < FPT; k2++) {
                    if (g_aflag[base + k2]) {
                        int p2 = scanb + base + k2;
                        if (r < need) {
                            g_cand[qn + r] = (int)(g_key[p2] & 0xffffffffu);
                            g_candpos[qn + r] = p2;
                        }
                        if (r == add - 1) s_lastp = p2;   // last taken position
                        r++;
                    }
                }
                __syncthreads();
                if (tid == 0) {
                    int nq = qn + add;
                    // if window over-delivered, consume only up to last taken:
                    // preserves invariant "all alive with pos < scanbase are queued"
                    int nsb = (total >= need && add > 0) ? (s_lastp + 1) : (scanb + NT);
                    g_qn = nq;
                    g_scanbase = nsb;
                    g_needtop = (nq < BB && nsb < NN) ? 1 : 0;
                }
            }
            gridbar(&s_gen);                                   // scan bar b
        }

        int found = g_qn;
        int epoch = g_epoch;
        if (found == 0) break;

        // ---- speculative BFS: one block per slot (v5 logic verbatim) ----
        if (blk < found) {
            int slot = blk;
            int* reg = (slot == 0) ? g_f0 : g_reg[slot];
            int cap  = (slot == 0) ? NN : REGC;
            int center = g_cand[slot];
            unsigned mykey = ((unsigned)epoch << 10) | (unsigned)(1023 - slot);
            if (tid == 0) {
                s_abort = 0; s_hi = 0;
                unsigned old = atomicMax(&g_mark[center], mykey);
                if ((old >> 10) == (unsigned)epoch) {
                    int os = 1023 - (int)(old & 1023u);
                    if (os < slot) {
                        atomicOr(&g_blkm[slot * 4 + (os >> 5)], 1u << (os & 31));
                        s_abort = 1;
                    } else if (os > slot) {
                        atomicExch(&g_conf[par][os], 1);
                    }
                }
                if (!s_abort) { reg[0] = center; s_hi = 1; }
            }
            __syncthreads();
            int lo = 0;
            for (int lev = 0; lev < depth; lev++) {
                if (s_abort) break;
                int hi = s_hi;
                if (hi == lo) break;
                if (tid == 0 && atomicAdd(&g_conf[par][slot], 0)) s_abort = 1;
                __syncthreads();
                if (s_abort) break;
                for (int i = lo + tid; i < hi; i += 256) {
                    int u = reg[i];
                    int e0 = g_indptr[u] + 1, e1 = g_indptr[u + 1];  // skip self slot
                    for (int e = e0; e < e1; e++) {
                        int w = g_adj[e];
                        if (g_cluster[w] != -1) continue;
                        unsigned old = atomicMax(&g_mark[w], mykey);
                        bool own;
                        if ((old >> 10) != (unsigned)epoch) own = true;
                        else {
                            int os = 1023 - (int)(old & 1023u);
                            if (os == slot) continue;
                            if (os < slot) {
                                atomicOr(&g_blkm[slot * 4 + (os >> 5)], 1u << (os & 31));
                                continue;
                            }
                            atomicExch(&g_conf[par][os], 1); own = true;
                        }
                        if (own) {
                            int j = atomicAdd(&s_hi, 1);
                            if (j < cap) reg[j] = w;
                            else { atomicExch(&g_conf[par][slot], 1); s_abort = 1; }
                        }
                    }
                }
                __syncthreads();
                lo = hi;
            }
            if (tid == 0) g_regsz[slot] = s_hi < cap ? s_hi : cap;
        }
        gridbar(&s_gen);                                       // bar 2

        // ---- commit analysis (v5): prefetch, serial walk, dead-skip ----
        for (int s = tid; s < found; s += 256) {
            unsigned m = g_mark[g_cand[s]];
            int ms = -1;
            if ((m >> 10) == (unsigned)epoch) ms = 1023 - (int)(m & 1023u);
            s_ms[s] = ms;
            s_flag[s] = g_conf[par][s];
        }
        for (int i = tid; i < found * 4; i += 256) s_B[i] = g_blkm[i];
        __syncthreads();
        if (tid == 0) {
            unsigned ex0 = 0, ex1 = 0, ex2 = 0, ex3 = 0;
            int stop = found, r = 0;
            for (int s = 0; s < found; s++) {
                int ms = s_ms[s];
                bool ok = false;
                if (ms == s && !s_flag[s]) {
                    ok = ((s_B[4*s+0] & ~ex0) == 0) && ((s_B[4*s+1] & ~ex1) == 0)
                      && ((s_B[4*s+2] & ~ex2) == 0) && ((s_B[4*s+3] & ~ex3) == 0);
                }
                if (ok) {
                    s_cls[s] = 1; s_rank[s] = r; r++;
                    if      (s < 32)  ex0 |= 1u << s;
                    else if (s < 64)  ex1 |= 1u << (s - 32);
                    else if (s < 96)  ex2 |= 1u << (s - 64);
                    else              ex3 |= 1u << (s - 96);
                } else if (ms >= 0 && ms < s &&
                           (((ms < 32 ? ex0 : ms < 64 ? ex1 : ms < 96 ? ex2 : ex3)
                             >> (ms & 31)) & 1u)) {
                    s_cls[s] = 0;                 // dead: center inside exact region
                } else {
                    stop = s; break;              // unknown -> stop
                }
            }
            s_stop = stop; s_ncommit = r;
        }
        __syncthreads();
        int stop = s_stop;                        // >= 1 (slot 0 always exact)
        int C = g_C;

        // committed slots write their regions with re-ranked ids
        if (blk < stop && s_cls[blk] == 1) {
            int* reg = (blk == 0) ? g_f0 : g_reg[blk];
            int sz = g_regsz[blk];
            int cid = C + s_rank[blk];
            for (int i = tid; i < sz; i += 256) g_cluster[reg[i]] = cid;
        }
        if (blk == 0) {
            for (int s = tid; s < stop; s += 256)
                if (s_cls[s] == 1) g_centers[C + s_rank[s]] = g_cand[s];
            if (tid == 0) {
                g_C = C + s_ncommit;
                g_epoch = epoch + 1;
            }
        }
        gridbar(&s_gen);                                       // bar 3 (commit-end)
    }
    if (blk == 0 && tid == 0) g_c = g_C;
}

// ---------------- concat reconstruction: key = (cluster<<32 | node) ----------------
__global__ void k_key2() {
    int i = blockIdx.x * blockDim.x + threadIdx.x;
    if (i >= MSEL) return;
    if (i < NN) {
        int cl = g_cluster[i];
        unsigned uc = (cl < 0) ? 0x7fffffffu : (unsigned)cl;
        g_key[i] = ((ull)uc << 32) | (unsigned)i;
    } else {
        g_key[i] = ~0ull;
    }
}

// After sort: position p holds key[p] = (cid[p]<<32 | oid[p]).
// Reference: clusters_buggy[v] = cid[ oid[v] ]  (cluster-id AT POSITION oid[v]).
__global__ void k_buggy() {
    int v = blockIdx.x * blockDim.x + threadIdx.x;
    if (v >= NN) return;
    int p = (int)(g_key[v] & 0xffffffffu);   // oid[v]
    int cid = 0;
    if (p >= 0 && p < NN) cid = (int)(g_key[p] >> 32);
    g_buggy[v] = cid;
}

// ---------------- edge dedup bitmap ----------------
__global__ void k_clearbmp() {
    int c = g_c; if (c > CMAXB) c = CMAXB;
    long long cw = (c + 63) >> 6;
    long long nw = (long long)c * cw;
    if (nw > (long long)BMPW) nw = BMPW;
    long long stride = (long long)gridDim.x * blockDim.x;
    for (long long i = blockIdx.x * (long long)blockDim.x + threadIdx.x; i < nw; i += stride)
        g_bmp[i] = 0ull;
}
__global__ void k_mark(const int* __restrict__ ei) {
    int e = blockIdx.x * blockDim.x + threadIdx.x;
    if (e >= EE) return;
    int s = ei[e], d = ei[EE + e];
    if (s == d) return;
    int a = g_buggy[s], b = g_buggy[d];
    if (a == b) return;
    int c = g_c;
    if (c > CMAXB) return;
    long long cw = (c + 63) >> 6;
    if (a < 0 || a >= c || b < 0 || b >= c) return;
    long long bit = (long long)a * (cw << 6) + b;
    atomicOr(&g_bmp[bit >> 6], 1ull << (bit & 63));
}
__global__ void k_rowcnt() {
    int a = blockIdx.x * blockDim.x + threadIdx.x;
    int c = g_c;
    if (a >= NN) return;
    if (a >= c || c > CMAXB) { g_rowcnt[a] = 0; return; }
    long long cw = (c + 63) >> 6;
    int cnt = 0;
    for (long long w = 0; w < cw; w++) cnt += __popcll(g_bmp[(long long)a * cw + w]);
    g_rowcnt[a] = cnt;
}

// ---------------- scan B ----------------
__global__ void k_scanB1() {
    __shared__ int sh[1024];
    int n = g_c; if (n > NN) n = NN;
    int b = blockIdx.x, tid = threadIdx.x;
    int idx = b * 1024 + tid;
    int v = (idx < n) ? g_rowcnt[idx] : 0;
    sh[tid] = v;
    __syncthreads();
    for (int d = 1; d < 1024; d <<= 1) {
        int t = (tid >= d) ? sh[tid - d] : 0;
        __syncthreads();
        sh[tid] += t;
        __syncthreads();
    }
    if (idx < n) g_rowincl[idx] = sh[tid];
    if (tid == 1023) g_aux[b] = sh[1023];
}
__global__ void k_scanB2() {
    int run = 0;
    for (int b = 0; b < 98; b++) { int t = g_aux[b]; g_aux[b] = run; run += t; }
}
__global__ void k_scanB3() {
    int n = g_c; if (n > NN) n = NN;
    int idx = blockIdx.x * 1024 + threadIdx.x;
    if (idx < n) g_rowincl[idx] += g_aux[idx >> 10];
}
__global__ void k_setE() {
    int c = g_c;
    g_Etot = (c > 0 && c <= NN) ? g_rowincl[c - 1] : 0;
}

// ---------------- x_p = segment_max ----------------
__global__ void k_xclear() {
    long long i = blockIdx.x * (long long)blockDim.x + threadIdx.x;
    if (i < (long long)NN * FD) g_enc[i] = 0u;
}
__global__ void k_xmax(const float* __restrict__ x) {
    long long i = blockIdx.x * (long long)blockDim.x + threadIdx.x;
    if (i >= (long long)NN * FD) return;
    int v = (int)(i / FD), f = (int)(i % FD);
    int cl = g_cluster[v];
    if (cl < 0 || cl >= NN) return;
    unsigned u = __float_as_uint(x[i]);
    u = (u >> 31) ? ~u : (u | 0x80000000u);
    atomicMax(&g_enc[(long long)cl * FD + f], u);
}
__global__ void k_xout(float* __restrict__ out, long long osz) {
    long long i = blockIdx.x * (long long)blockDim.x + threadIdx.x;
    if (i >= (long long)g_c * FD || i >= osz) return;
    unsigned u = g_enc[i];
    unsigned bits = (u & 0x80000000u) ? (u ^ 0x80000000u) : ~u;
    out[i] = __uint_as_float(bits);
}

// ---------------- new_ei emission ----------------
__global__ void k_emit(float* __restrict__ out, long long osz) {
    int a = blockIdx.x * blockDim.x + threadIdx.x;
    int c = g_c;
    if (a >= c || c > CMAXB) return;
    long long cw = (c + 63) >> 6;
    int base = g_rowincl[a] - g_rowcnt[a];
    long long eoff = (long long)FD * c;
    int Et = g_Etot;
    int cnt = 0;
    for (long long w = 0; w < cw; w++) {
        ull u = g_bmp[(long long)a * cw + w];
        while (u) {
            int bpos = __ffsll((long long)u) - 1;
            int b = (int)(w * 64 + bpos);
            long long p0 = eoff + base + cnt;
            long long p1 = eoff + Et + base + cnt;
            if (p0 >= 0 && p0 < osz) out[p0] = (float)a;
            if (p1 >= 0 && p1 < osz) out[p1] = (float)b;
            cnt++;
            u &= (u - 1);
        }
    }
}

// ---------------- pos_p ----------------
__global__ void k_posout(const float* __restrict__ pos, float* __restrict__ out,
                         long long osz) {
    int i = blockIdx.x * blockDim.x + threadIdx.x;
    int c = g_c;
    if (i >= 3 * c) return;
    int j = i / 3, d = i % 3;
    int ctr = g_centers[j];
    if (ctr < 0 || ctr >= NN) return;
    long long off = (long long)FD * c + 2LL * g_Etot + i;
    if (off >= 0 && off < osz)
        out[off] = pos[(long long)ctr * 3 + d];
}

// ---------------- host-side sort driver (launches only) ----------------
static void run_sort() {
    k_sort_local<<<MSEL / 2048, 1024>>>();
    for (int k2 = 4096; k2 <= MSEL; k2 <<= 1) {
        for (int j = k2 >> 1; j >= 2048; j >>= 1)
            k_bitonic<<<MSEL / 256, 256>>>(j, k2);
        k_merge_local<<<MSEL / 2048, 1024>>>(k2);
    }
}

// ---------------- launch ----------------
extern "C" void kernel_launch(void* const* d_in, const int* in_sizes, int n_in,
                              void* d_out, int out_size) {
    const float* x     = (const float*)d_in[0];
    const int*   ei    = (const int*)d_in[1];
    const float* pos   = (const float*)d_in[2];
    const float* wroot = (const float*)d_in[3];
    const float* wrel  = (const float*)d_in[4];
    const float* bb    = (const float*)d_in[5];
    float* out = (float*)d_out;
    long long osz = (long long)out_size;

    k_init<<<(NN + 255) / 256, 256>>>();
    k_dots<<<(NN + 7) / 8, 256>>>(x, pos, wroot, wrel);
    k_edge1<<<(EE + 255) / 256, 256>>>(ei);
    k_minred<<<(NN + 255) / 256, 256>>>();
    k_kcalc<<<1, 1>>>();
    k_key<<<MSEL / 256, 256>>>(bb);
    run_sort();                                   // sel order
    k_scanA1<<<98, 1024>>>();
    k_scanA2<<<1, 1>>>();
    k_scanA3<<<98, 1024>>>();
    k_fillself<<<98, 1024>>>();
    k_adjE<<<(EE + 255) / 256, 256>>>(ei);
    k_peel7<<<NBLK, 256>>>();
    k_key2<<<MSEL / 256, 256>>>();
    run_sort();                                   // concat order (cluster, node)
    k_clearbmp<<<2048, 256>>>();
    k_buggy<<<(NN + 255) / 256, 256>>>();
    k_mark<<<(EE + 255) / 256, 256>>>(ei);
    k_rowcnt<<<(NN + 255) / 256, 256>>>();
    k_scanB1<<<98, 1024>>>();
    k_scanB2<<<1, 1>>>();
    k_scanB3<<<98, 1024>>>();
    k_setE<<<1, 1>>>();
    k_xclear<<<(NN * FD + 255) / 256, 256>>>();
    k_xmax<<<(NN * FD + 255) / 256, 256>>>(x);
    k_xout<<<(NN * FD + 255) / 256, 256>>>(out, osz);
    k_emit<<<(NN + 255) / 256, 256>>>(out, osz);
    k_posout<<<(3 * NN + 255) / 256, 256>>>(pos, out, osz);
}

// round 15
// speedup vs baseline: 1.6460x; 1.5669x over previous
#include <cuda_runtime.h>
#include <math.h>
#include <stdint.h>

typedef unsigned long long ull;

// ---------------- problem constants ----------------
#define NN 100000
#define EE 1600000
#define FD 125
#define PD 3
#define MSEL 131072            // pow2 >= NN
#define NBLK 128               // persistent blocks (all wave-1 resident)
#define NT (NBLK*256)          // grid threads = 32768
#define BB 128                 // max speculative batch = NBLK
#define QTH 64                 // top-up threshold: scan only when queue < QTH
#define REGC 16384             // per-slot region capacity (slots > 0)
#define BMPW (1u<<24)          // 2^24 words = 2^30 bits bitmap (c <= 32768)
#define CMAXB 32768
#define QSCALE 17179869184.0   // 2^34 fixed-point scale
#define QINV   (1.0/17179869184.0)

// ---------------- static device scratch ----------------
__device__ double  g_sroot[NN];
__device__ double  g_srel[NN];
__device__ long long g_qrel[NN];
__device__ ull     g_relfix[NN];
__device__ int     g_deg[NN];
__device__ int     g_indptr[NN + 1];
__device__ int     g_fill[NN];
__device__ int     g_adj[NN + EE];
__device__ ull     g_key[MSEL];
__device__ int     g_cluster[NN];
__device__ int     g_centers[NN];
__device__ int     g_buggy[NN];
__device__ int     g_f0[NN];           // slot-0 region list (never truncates)
__device__ int     g_reg[BB][REGC];    // per-slot region lists (slots 1..BB-1)
__device__ int     g_regsz[BB];
__device__ unsigned g_mark[NN];        // speculative marks: (epoch<<10)|(1023-slot)
__device__ int     g_cand[BB];
__device__ int     g_candpos[BB];
__device__ int     g_conf[2][BB];      // HARD flags, double-buffered by round parity
__device__ unsigned g_blkm[BB * 4];    // blocked-by bitmask (lost-at-touch), per slot
__device__ int     g_aflag[NT];
__device__ unsigned int g_enc[NN * FD];
__device__ ull     g_bmp[BMPW];        // 128MB
__device__ int     g_rowcnt[NN];
__device__ int     g_rowincl[NN];
__device__ int     g_aux[128];
__device__ int     g_selfcnt;
__device__ int     g_degmin;
__device__ int     g_depth;
__device__ int     g_c;
__device__ int     g_Etot;
// persistent-kernel coordination
__device__ int     g_epoch, g_C, g_qn, g_needtop, g_scanbase;
__device__ int     g_barArrive, g_barGen;

// ---------------- init ----------------
__global__ void k_init() {
    int v = blockIdx.x * blockDim.x + threadIdx.x;
    if (v < NN) {
        g_deg[v] = 1;        // appended self-loop
        g_relfix[v] = 0ull;
        g_cluster[v] = -1;
        g_mark[v] = 0u;
    }
    if (v < BB) { g_conf[0][v] = 0; g_conf[1][v] = 0; g_regsz[v] = 0; }
    if (v < BB * 4) g_blkm[v] = 0u;
    if (v == 0) {
        g_selfcnt = 0; g_degmin = 0x7fffffff;
        g_epoch = 1; g_C = 0;
        g_qn = 0; g_needtop = 1; g_scanbase = 0;
        g_barArrive = 0; g_barGen = 0;
    }
}

// ---------------- per-node 128-dim dots (fp64, warp per node) ----------------
__global__ void k_dots(const float* __restrict__ x, const float* __restrict__ pos,
                       const float* __restrict__ wroot, const float* __restrict__ wrel) {
    int tid = threadIdx.x;
    int warp = tid >> 5, lane = tid & 31;
    int v = blockIdx.x * 8 + warp;
    if (v >= NN) return;
    double ar = 0.0, rr = 0.0;
    for (int d = lane; d < 128; d += 32) {
        double val = (d < FD) ? (double)x[(size_t)v * FD + d]
                              : (double)pos[(size_t)v * PD + (d - FD)];
        ar += val * (double)wroot[d];
        rr += val * (double)wrel[d];
    }
    for (int o = 16; o > 0; o >>= 1) {
        ar += __shfl_down_sync(0xffffffffu, ar, o);
        rr += __shfl_down_sync(0xffffffffu, rr, o);
    }
    if (lane == 0) {
        g_sroot[v] = ar;
        g_srel[v]  = rr;
        g_qrel[v]  = llrint(rr * QSCALE);
    }
}

// ---------------- edge pass ----------------
__global__ void k_edge1(const int* __restrict__ ei) {
    int e = blockIdx.x * blockDim.x + threadIdx.x;
    if (e >= EE) return;
    int s = ei[e], d = ei[EE + e];
    if (s == d) {
        atomicAdd(&g_selfcnt, 1);
    } else {
        atomicAdd(&g_deg[s], 1);
        atomicAdd(&g_relfix[d], (ull)g_qrel[s]);
    }
}

__global__ void k_minred() {
    int v = blockIdx.x * blockDim.x + threadIdx.x;
    if (v < NN) atomicMin(&g_degmin, g_deg[v]);
}

__global__ void k_kcalc() {
    long long kept = (long long)EE - g_selfcnt;
    double mean = (double)(kept + NN) / (double)NN;
    double b = log(mean - (double)g_degmin);
    double a = log(1.0 / 0.8);
    long long kk = (long long)ceil(a / b);
    int d = (int)kk + 2;
    if (d < 1) d = 1;
    if (d > 16) d = 16;
    g_depth = d;
}

// ---------------- score -> sortable key ----------------
__global__ void k_key(const float* __restrict__ bptr) {
    int i = blockIdx.x * blockDim.x + threadIdx.x;
    if (i >= MSEL) return;
    if (i < NN) {
        double sc = g_sroot[i] + g_srel[i] + (double)(long long)g_relfix[i] * QINV
                  + (double)bptr[0];
        float f = (float)sc;
        unsigned u = __float_as_uint(f);
        u = (u >> 31) ? ~u : (u | 0x80000000u);
        unsigned du = ~u;
        g_key[i] = ((ull)du << 32) | (unsigned)i;
    } else {
        g_key[i] = ~0ull;
    }
}

// ---------------- bitonic sort: global stage + smem-fused stages ----------------
__global__ void k_bitonic(int j, int k2) {
    int i = blockIdx.x * blockDim.x + threadIdx.x;
    int ixj = i ^ j;
    if (ixj > i) {
        ull a = g_key[i], b = g_key[ixj];
        bool up = ((i & k2) == 0);
        if ((a > b) == up) { g_key[i] = b; g_key[ixj] = a; }
    }
}

__global__ void __launch_bounds__(1024) k_sort_local() {
    __shared__ ull sh[2048];
    int base = blockIdx.x * 2048, t = threadIdx.x;
    sh[t] = g_key[base + t];
    sh[t + 1024] = g_key[base + t + 1024];
    __syncthreads();
    for (int k2 = 2; k2 <= 2048; k2 <<= 1) {
        for (int j = k2 >> 1; j > 0; j >>= 1) {
            #pragma unroll
            for (int q = 0; q < 2; q++) {
                int i = t + q * 1024;
                int ixj = i ^ j;
                if (ixj > i) {
                    bool up = (((base + i) & k2) == 0);
                    ull a = sh[i], b = sh[ixj];
                    if ((a > b) == up) { sh[i] = b; sh[ixj] = a; }
                }
            }
            __syncthreads();
        }
    }
    g_key[base + t] = sh[t];
    g_key[base + t + 1024] = sh[t + 1024];
}

__global__ void __launch_bounds__(1024) k_merge_local(int k2) {
    __shared__ ull sh[2048];
    int base = blockIdx.x * 2048, t = threadIdx.x;
    sh[t] = g_key[base + t];
    sh[t + 1024] = g_key[base + t + 1024];
    __syncthreads();
    for (int j = 1024; j > 0; j >>= 1) {
        #pragma unroll
        for (int q = 0; q < 2; q++) {
            int i = t + q * 1024;
            int ixj = i ^ j;
            if (ixj > i) {
                bool up = (((base + i) & k2) == 0);
                ull a = sh[i], b = sh[ixj];
                if ((a > b) == up) { sh[i] = b; sh[ixj] = a; }
            }
        }
        __syncthreads();
    }
    g_key[base + t] = sh[t];
    g_key[base + t + 1024] = sh[t + 1024];
}

// ---------------- scan A: deg -> indptr ----------------
__global__ void k_scanA1() {
    __shared__ int sh[1024];
    int b = blockIdx.x, tid = threadIdx.x;
    int idx = b * 1024 + tid;
    int v = (idx < NN) ? g_deg[idx] : 0;
    sh[tid] = v;
    __syncthreads();
    for (int d = 1; d < 1024; d <<= 1) {
        int t = (tid >= d) ? sh[tid - d] : 0;
        __syncthreads();
        sh[tid] += t;
        __syncthreads();
    }
    if (idx < NN) g_indptr[idx + 1] = sh[tid];
    if (tid == 1023) g_aux[b] = sh[1023];
}
__global__ void k_scanA2() {
    int run = 0;
    for (int b = 0; b < 98; b++) { int t = g_aux[b]; g_aux[b] = run; run += t; }
    g_indptr[0] = 0;
}
__global__ void k_scanA3() {
    int idx = blockIdx.x * 1024 + threadIdx.x;
    if (idx < NN) g_indptr[idx + 1] += g_aux[idx >> 10];
}

__global__ void k_fillself() {
    int v = blockIdx.x * 1024 + threadIdx.x;
    if (v < NN) {
        int p = g_indptr[v];
        g_adj[p] = v;          // self-loop at slot 0
        g_fill[v] = p + 1;
    }
}
__global__ void k_adjE(const int* __restrict__ ei) {
    int e = blockIdx.x * blockDim.x + threadIdx.x;
    if (e >= EE) return;
    int s = ei[e], d = ei[EE + e];
    if (s != d) g_adj[atomicAdd(&g_fill[s], 1)] = d;
}

// -------- grid barrier (all NBLK blocks resident; volatile poll + backoff) --------
__device__ __forceinline__ void gridbar(int* sgen) {
    __syncthreads();
    if (threadIdx.x == 0) {
        int g = *sgen;
        __threadfence();
        if (atomicAdd(&g_barArrive, 1) == NBLK - 1) {
            atomicExch(&g_barArrive, 0);
            __threadfence();
            atomicAdd(&g_barGen, 1);
        } else {
            while (((volatile int*)&g_barGen)[0] < g + 1) __nanosleep(64);
        }
        __threadfence();
        *sgen = g + 1;
    }
    __syncthreads();
}

// ------- speculative peel v8: lazy top-up queue (QTH), parallel compaction -------
__global__ void __launch_bounds__(256) k_peel8() {
    __shared__ int s_gen, s_abort, s_hi, s_stop, s_ncommit, s_lastp;
    __shared__ int s_pref[256];
    __shared__ int s_tmpc[BB], s_tmpp[BB];
    __shared__ int s_ms[BB];
    __shared__ int s_flag[BB];
    __shared__ unsigned s_B[BB * 4];
    __shared__ int s_cls[BB];
    __shared__ int s_rank[BB];
    int tid = threadIdx.x;
    int blk = blockIdx.x;
    if (tid == 0) s_gen = g_barGen;
    __syncthreads();
    int depth = g_depth;

    for (int round = 0; round < NN; round++) {
        int par = round & 1;
        // clear next round's HARD flag buffer + own soft-block mask.
        if (tid == 0) g_conf[par ^ 1][blk] = 0;
        if (tid < 4) g_blkm[blk * 4 + tid] = 0u;

        // ---- queue compaction (block 0, parallel): drop claimed, keep order ----
        if (blk == 0) {
            int qn = g_qn;
            int al = 0, cnd = 0, cps = 0;
            if (tid < qn) {
                cnd = g_cand[tid];
                cps = g_candpos[tid];
                al = (g_cluster[cnd] == -1) ? 1 : 0;
            }
            s_pref[tid] = al;
            __syncthreads();
            for (int d = 1; d < 256; d <<= 1) {
                int v = (tid >= d) ? s_pref[tid - d] : 0;
                __syncthreads();
                s_pref[tid] += v;
                __syncthreads();
            }
            if (al) { int w = s_pref[tid] - 1; s_tmpc[w] = cnd; s_tmpp[w] = cps; }
            __syncthreads();
            int w = s_pref[255];
            if (tid < w) { g_cand[tid] = s_tmpc[tid]; g_candpos[tid] = s_tmpp[tid]; }
            if (tid == 0) {
                g_qn = w;
                g_needtop = (w < QTH && g_scanbase < NN) ? 1 : 0;
            }
        }
        gridbar(&s_gen);                                       // bar 1

        // ---- lazy top-up scan: fill queue to BB (runs ~1 in 5 rounds) ----
        while (g_needtop) {
            int scanb = g_scanbase;
            int tg = blk * 256 + tid;
            int pos = scanb + tg;
            int fl = 0;
            if (pos < NN) {
                int s = (int)(g_key[pos] & 0xffffffffu);
                if (g_cluster[s] == -1) fl = 1;
            }
            g_aflag[tg] = fl;
            gridbar(&s_gen);                                   // scan bar a
            if (blk == 0) {
                int qn = g_qn;
                int need = BB - qn;
                const int FPT = NT / 256;                      // 128 flags/thread
                int base = tid * FPT;
                int cnt = 0;
                for (int k2 = 0; k2 < FPT; k2++) cnt += g_aflag[base + k2];
                s_pref[tid] = cnt;
                __syncthreads();
                for (int d = 1; d < 256; d <<= 1) {
                    int v = (tid >= d) ? s_pref[tid - d] : 0;
                    __syncthreads();
                    s_pref[tid] += v;
                    __syncthreads();
                }
                int excl = s_pref[tid] - cnt;
                int total = s_pref[255];
                int add = total < need ? total : need;
                int r = excl;
                for (int k2 = 0; k2 < FPT; k2++) {
                    if (g_aflag[base + k2]) {
                        int p2 = scanb + base + k2;
                        if (r < need) {
                            g_cand[qn + r] = (int)(g_key[p2] & 0xffffffffu);
                            g_candpos[qn + r] = p2;
                        }
                        if (r == add - 1) s_lastp = p2;   // last taken position
                        r++;
                    }
                }
                __syncthreads();
                if (tid == 0) {
                    int nq = qn + add;
                    // if window over-delivered, consume only up to last taken:
                    // preserves "all alive with pos < scanbase are queued"
                    int nsb = (total >= need && add > 0) ? (s_lastp + 1) : (scanb + NT);
                    g_qn = nq;
                    g_scanbase = nsb;
                    g_needtop = (nq < BB && nsb < NN) ? 1 : 0;
                }
            }
            gridbar(&s_gen);                                   // scan bar b
        }

        int found = g_qn;
        int epoch = g_epoch;
        if (found == 0) break;

        // ---- speculative BFS: one block per slot (v5 logic verbatim) ----
        if (blk < found) {
            int slot = blk;
            int* reg = (slot == 0) ? g_f0 : g_reg[slot];
            int cap  = (slot == 0) ? NN : REGC;
            int center = g_cand[slot];
            unsigned mykey = ((unsigned)epoch << 10) | (unsigned)(1023 - slot);
            if (tid == 0) {
                s_abort = 0; s_hi = 0;
                unsigned old = atomicMax(&g_mark[center], mykey);
                if ((old >> 10) == (unsigned)epoch) {
                    int os = 1023 - (int)(old & 1023u);
                    if (os < slot) {
                        atomicOr(&g_blkm[slot * 4 + (os >> 5)], 1u << (os & 31));
                        s_abort = 1;
                    } else if (os > slot) {
                        atomicExch(&g_conf[par][os], 1);
                    }
                }
                if (!s_abort) { reg[0] = center; s_hi = 1; }
            }
            __syncthreads();
            int lo = 0;
            for (int lev = 0; lev < depth; lev++) {
                if (s_abort) break;
                int hi = s_hi;
                if (hi == lo) break;
                if (tid == 0 && atomicAdd(&g_conf[par][slot], 0)) s_abort = 1;
                __syncthreads();
                if (s_abort) break;
                for (int i = lo + tid; i < hi; i += 256) {
                    int u = reg[i];
                    int e0 = g_indptr[u] + 1, e1 = g_indptr[u + 1];  // skip self slot
                    for (int e = e0; e < e1; e++) {
                        int w = g_adj[e];
                        if (g_cluster[w] != -1) continue;
                        unsigned old = atomicMax(&g_mark[w], mykey);
                        bool own;
                        if ((old >> 10) != (unsigned)epoch) own = true;
                        else {
                            int os = 1023 - (int)(old & 1023u);
                            if (os == slot) continue;
                            if (os < slot) {
                                atomicOr(&g_blkm[slot * 4 + (os >> 5)], 1u << (os & 31));
                                continue;
                            }
                            atomicExch(&g_conf[par][os], 1); own = true;
                        }
                        if (own) {
                            int j = atomicAdd(&s_hi, 1);
                            if (j < cap) reg[j] = w;
                            else { atomicExch(&g_conf[par][slot], 1); s_abort = 1; }
                        }
                    }
                }
                __syncthreads();
                lo = hi;
            }
            if (tid == 0) g_regsz[slot] = s_hi < cap ? s_hi : cap;
        }
        gridbar(&s_gen);                                       // bar 2

        // ---- commit analysis (v5): prefetch, serial walk, dead-skip ----
        for (int s = tid; s < found; s += 256) {
            unsigned m = g_mark[g_cand[s]];
            int ms = -1;
            if ((m >> 10) == (unsigned)epoch) ms = 1023 - (int)(m & 1023u);
            s_ms[s] = ms;
            s_flag[s] = g_conf[par][s];
        }
        for (int i = tid; i < found * 4; i += 256) s_B[i] = g_blkm[i];
        __syncthreads();
        if (tid == 0) {
            unsigned ex0 = 0, ex1 = 0, ex2 = 0, ex3 = 0;
            int stop = found, r = 0;
            for (int s = 0; s < found; s++) {
                int ms = s_ms[s];
                bool ok = false;
                if (ms == s && !s_flag[s]) {
                    ok = ((s_B[4*s+0] & ~ex0) == 0) && ((s_B[4*s+1] & ~ex1) == 0)
                      && ((s_B[4*s+2] & ~ex2) == 0) && ((s_B[4*s+3] & ~ex3) == 0);
                }
                if (ok) {
                    s_cls[s] = 1; s_rank[s] = r; r++;
                    if      (s < 32)  ex0 |= 1u << s;
                    else if (s < 64)  ex1 |= 1u << (s - 32);
                    else if (s < 96)  ex2 |= 1u << (s - 64);
                    else              ex3 |= 1u << (s - 96);
                } else if (ms >= 0 && ms < s &&
                           (((ms < 32 ? ex0 : ms < 64 ? ex1 : ms < 96 ? ex2 : ex3)
                             >> (ms & 31)) & 1u)) {
                    s_cls[s] = 0;                 // dead: center inside exact region
                } else {
                    stop = s; break;              // unknown -> stop
                }
            }
            s_stop = stop; s_ncommit = r;
        }
        __syncthreads();
        int stop = s_stop;                        // >= 1 (slot 0 always exact)
        int C = g_C;

        // committed slots write their regions with re-ranked ids
        if (blk < stop && s_cls[blk] == 1) {
            int* reg = (blk == 0) ? g_f0 : g_reg[blk];
            int sz = g_regsz[blk];
            int cid = C + s_rank[blk];
            for (int i = tid; i < sz; i += 256) g_cluster[reg[i]] = cid;
        }
        if (blk == 0) {
            for (int s = tid; s < stop; s += 256)
                if (s_cls[s] == 1) g_centers[C + s_rank[s]] = g_cand[s];
            if (tid == 0) {
                g_C = C + s_ncommit;
                g_epoch = epoch + 1;
            }
        }
        gridbar(&s_gen);                                       // bar 3 (commit-end)
    }
    if (blk == 0 && tid == 0) g_c = g_C;
}

// ---------------- concat reconstruction: key = (cluster<<32 | node) ----------------
__global__ void k_key2() {
    int i = blockIdx.x * blockDim.x + threadIdx.x;
    if (i >= MSEL) return;
    if (i < NN) {
        int cl = g_cluster[i];
        unsigned uc = (cl < 0) ? 0x7fffffffu : (unsigned)cl;
        g_key[i] = ((ull)uc << 32) | (unsigned)i;
    } else {
        g_key[i] = ~0ull;
    }
}

// After sort: position p holds key[p] = (cid[p]<<32 | oid[p]).
// Reference: clusters_buggy[v] = cid[ oid[v] ]  (cluster-id AT POSITION oid[v]).
__global__ void k_buggy() {
    int v = blockIdx.x * blockDim.x + threadIdx.x;
    if (v >= NN) return;
    int p = (int)(g_key[v] & 0xffffffffu);   // oid[v]
    int cid = 0;
    if (p >= 0 && p < NN) cid = (int)(g_key[p] >> 32);
    g_buggy[v] = cid;
}

// ---------------- edge dedup bitmap ----------------
__global__ void k_clearbmp() {
    int c = g_c; if (c > CMAXB) c = CMAXB;
    long long cw = (c + 63) >> 6;
    long long nw = (long long)c * cw;
    if (nw > (long long)BMPW) nw = BMPW;
    long long stride = (long long)gridDim.x * blockDim.x;
    for (long long i = blockIdx.x * (long long)blockDim.x + threadIdx.x; i < nw; i += stride)
        g_bmp[i] = 0ull;
}
__global__ void k_mark(const int* __restrict__ ei) {
    int e = blockIdx.x * blockDim.x + threadIdx.x;
    if (e >= EE) return;
    int s = ei[e], d = ei[EE + e];
    if (s == d) return;
    int a = g_buggy[s], b = g_buggy[d];
    if (a == b) return;
    int c = g_c;
    if (c > CMAXB) return;
    long long cw = (c + 63) >> 6;
    if (a < 0 || a >= c || b < 0 || b >= c) return;
    long long bit = (long long)a * (cw << 6) + b;
    atomicOr(&g_bmp[bit >> 6], 1ull << (bit & 63));
}
__global__ void k_rowcnt() {
    int a = blockIdx.x * blockDim.x + threadIdx.x;
    int c = g_c;
    if (a >= NN) return;
    if (a >= c || c > CMAXB) { g_rowcnt[a] = 0; return; }
    long long cw = (c + 63) >> 6;
    int cnt = 0;
    for (long long w = 0; w < cw; w++) cnt += __popcll(g_bmp[(long long)a * cw + w]);
    g_rowcnt[a] = cnt;
}

// ---------------- scan B ----------------
__global__ void k_scanB1() {
    __shared__ int sh[1024];
    int n = g_c; if (n > NN) n = NN;
    int b = blockIdx.x, tid = threadIdx.x;
    int idx = b * 1024 + tid;
    int v = (idx < n) ? g_rowcnt[idx] : 0;
    sh[tid] = v;
    __syncthreads();
    for (int d = 1; d < 1024; d <<= 1) {
        int t = (tid >= d) ? sh[tid - d] : 0;
        __syncthreads();
        sh[tid] += t;
        __syncthreads();
    }
    if (idx < n) g_rowincl[idx] = sh[tid];
    if (tid == 1023) g_aux[b] = sh[1023];
}
__global__ void k_scanB2() {
    int run = 0;
    for (int b = 0; b < 98; b++) { int t = g_aux[b]; g_aux[b] = run; run += t; }
}
__global__ void k_scanB3() {
    int n = g_c; if (n > NN) n = NN;
    int idx = blockIdx.x * 1024 + threadIdx.x;
    if (idx < n) g_rowincl[idx] += g_aux[idx >> 10];
}
__global__ void k_setE() {
    int c = g_c;
    g_Etot = (c > 0 && c <= NN) ? g_rowincl[c - 1] : 0;
}

// ---------------- x_p = segment_max ----------------
__global__ void k_xclear() {
    long long i = blockIdx.x * (long long)blockDim.x + threadIdx.x;
    if (i < (long long)NN * FD) g_enc[i] = 0u;
}
__global__ void k_xmax(const float* __restrict__ x) {
    long long i = blockIdx.x * (long long)blockDim.x + threadIdx.x;
    if (i >= (long long)NN * FD) return;
    int v = (int)(i / FD), f = (int)(i % FD);
    int cl = g_cluster[v];
    if (cl < 0 || cl >= NN) return;
    unsigned u = __float_as_uint(x[i]);
    u = (u >> 31) ? ~u : (u | 0x80000000u);
    atomicMax(&g_enc[(long long)cl * FD + f], u);
}
__global__ void k_xout(float* __restrict__ out, long long osz) {
    long long i = blockIdx.x * (long long)blockDim.x + threadIdx.x;
    if (i >= (long long)g_c * FD || i >= osz) return;
    unsigned u = g_enc[i];
    unsigned bits = (u & 0x80000000u) ? (u ^ 0x80000000u) : ~u;
    out[i] = __uint_as_float(bits);
}

// ---------------- new_ei emission ----------------
__global__ void k_emit(float* __restrict__ out, long long osz) {
    int a = blockIdx.x * blockDim.x + threadIdx.x;
    int c = g_c;
    if (a >= c || c > CMAXB) return;
    long long cw = (c + 63) >> 6;
    int base = g_rowincl[a] - g_rowcnt[a];
    long long eoff = (long long)FD * c;
    int Et = g_Etot;
    int cnt = 0;
    for (long long w = 0; w < cw; w++) {
        ull u = g_bmp[(long long)a * cw + w];
        while (u) {
            int bpos = __ffsll((long long)u) - 1;
            int b = (int)(w * 64 + bpos);
            long long p0 = eoff + base + cnt;
            long long p1 = eoff + Et + base + cnt;
            if (p0 >= 0 && p0 < osz) out[p0] = (float)a;
            if (p1 >= 0 && p1 < osz) out[p1] = (float)b;
            cnt++;
            u &= (u - 1);
        }
    }
}

// ---------------- pos_p ----------------
__global__ void k_posout(const float* __restrict__ pos, float* __restrict__ out,
                         long long osz) {
    int i = blockIdx.x * blockDim.x + threadIdx.x;
    int c = g_c;
    if (i >= 3 * c) return;
    int j = i / 3, d = i % 3;
    int ctr = g_centers[j];
    if (ctr < 0 || ctr >= NN) return;
    long long off = (long long)FD * c + 2LL * g_Etot + i;
    if (off >= 0 && off < osz)
        out[off] = pos[(long long)ctr * 3 + d];
}

// ---------------- host-side sort driver (launches only) ----------------
static void run_sort() {
    k_sort_local<<<MSEL / 2048, 1024>>>();
    for (int k2 = 4096; k2 <= MSEL; k2 <<= 1) {
        for (int j = k2 >> 1; j >= 2048; j >>= 1)
            k_bitonic<<<MSEL / 256, 256>>>(j, k2);
        k_merge_local<<<MSEL / 2048, 1024>>>(k2);
    }
}

// ---------------- launch ----------------
extern "C" void kernel_launch(void* const* d_in, const int* in_sizes, int n_in,
                              void* d_out, int out_size) {
    const float* x     = (const float*)d_in[0];
    const int*   ei    = (const int*)d_in[1];
    const float* pos   = (const float*)d_in[2];
    const float* wroot = (const float*)d_in[3];
    const float* wrel  = (const float*)d_in[4];
    const float* bb    = (const float*)d_in[5];
    float* out = (float*)d_out;
    long long osz = (long long)out_size;

    k_init<<<(NN + 255) / 256, 256>>>();
    k_dots<<<(NN + 7) / 8, 256>>>(x, pos, wroot, wrel);
    k_edge1<<<(EE + 255) / 256, 256>>>(ei);
    k_minred<<<(NN + 255) / 256, 256>>>();
    k_kcalc<<<1, 1>>>();
    k_key<<<MSEL / 256, 256>>>(bb);
    run_sort();                                   // sel order
    k_scanA1<<<98, 1024>>>();
    k_scanA2<<<1, 1>>>();
    k_scanA3<<<98, 1024>>>();
    k_fillself<<<98, 1024>>>();
    k_adjE<<<(EE + 255) / 256, 256>>>(ei);
    k_peel8<<<NBLK, 256>>>();
    k_key2<<<MSEL / 256, 256>>>();
    run_sort();                                   // concat order (cluster, node)
    k_clearbmp<<<2048, 256>>>();
    k_buggy<<<(NN + 255) / 256, 256>>>();
    k_mark<<<(EE + 255) / 256, 256>>>(ei);
    k_rowcnt<<<(NN + 255) / 256, 256>>>();
    k_scanB1<<<98, 1024>>>();
    k_scanB2<<<1, 1>>>();
    k_scanB3<<<98, 1024>>>();
    k_setE<<<1, 1>>>();
    k_xclear<<<(NN * FD + 255) / 256, 256>>>();
    k_xmax<<<(NN * FD + 255) / 256, 256>>>(x);
    k_xout<<<(NN * FD + 255) / 256, 256>>>(out, osz);
    k_emit<<<(NN + 255) / 256, 256>>>(out, osz);
    k_posout<<<(3 * NN + 255) / 256, 256>>>(pos, out, osz);
}

// round 16
// speedup vs baseline: 1.7052x; 1.0360x over previous
#include <cuda_runtime.h>
#include <math.h>
#include <stdint.h>

typedef unsigned long long ull;

// ---------------- problem constants ----------------
#define NN 100000
#define EE 1600000
#define FD 125
#define PD 3
#define MSEL 131072            // pow2 >= NN
#define NBLK 128               // persistent blocks (all wave-1 resident)
#define NT (NBLK*256)          // grid threads = 32768
#define BB 128                 // max speculative batch = NBLK
#define QTH 64                 // top-up threshold: scan only when queue < QTH
#define REGC 16384             // per-slot region capacity (slots > 0)
#define BMPW (1u<<24)          // 2^24 words = 2^30 bits bitmap (c <= 32768)
#define CMAXB 32768
#define QSCALE 17179869184.0   // 2^34 fixed-point scale
#define QINV   (1.0/17179869184.0)

// ---------------- static device scratch ----------------
__device__ double  g_sroot[NN];
__device__ double  g_srel[NN];
__device__ long long g_qrel[NN];
__device__ ull     g_relfix[NN];
__device__ int     g_deg[NN];
__device__ int     g_indptr[NN + 1];
__device__ int     g_fill[NN];
__device__ int     g_adj[NN + EE];
__device__ ull     g_key[MSEL];
__device__ int     g_cluster[NN];
__device__ int     g_centers[NN];
__device__ int     g_buggy[NN];
__device__ int     g_f0[NN];           // slot-0 region list (never truncates)
__device__ int     g_reg[BB][REGC];    // per-slot region lists (slots 1..BB-1)
__device__ int     g_regsz[BB];
__device__ unsigned g_mark[NN];        // speculative marks: (epoch<<10)|(1023-slot)
__device__ int     g_cand[BB];         // top-up transfer buffer only
__device__ int     g_conf[2][BB];      // HARD flags, double-buffered by round parity
__device__ unsigned g_blkm[BB * 4];    // blocked-by bitmask (lost-at-touch), per slot
__device__ int     g_aflag[NT];
__device__ unsigned int g_enc[NN * FD];
__device__ ull     g_bmp[BMPW];        // 128MB
__device__ int     g_rowcnt[NN];
__device__ int     g_rowincl[NN];
__device__ int     g_aux[128];
__device__ int     g_selfcnt;
__device__ int     g_degmin;
__device__ int     g_depth;
__device__ int     g_c;
__device__ int     g_Etot;
// persistent-kernel coordination
__device__ int     g_C, g_qn, g_needtop, g_scanbase;
__device__ int     g_barArrive, g_barGen;

// ---------------- init ----------------
__global__ void k_init() {
    int v = blockIdx.x * blockDim.x + threadIdx.x;
    if (v < NN) {
        g_deg[v] = 1;        // appended self-loop
        g_relfix[v] = 0ull;
        g_cluster[v] = -1;
        g_mark[v] = 0u;
    }
    if (v < BB) { g_conf[0][v] = 0; g_conf[1][v] = 0; g_regsz[v] = 0; }
    if (v < BB * 4) g_blkm[v] = 0u;
    if (v == 0) {
        g_selfcnt = 0; g_degmin = 0x7fffffff;
        g_C = 0;
        g_qn = 0; g_needtop = 1; g_scanbase = 0;
        g_barArrive = 0; g_barGen = 0;
    }
}

// ---------------- per-node 128-dim dots (fp64, warp per node) ----------------
__global__ void k_dots(const float* __restrict__ x, const float* __restrict__ pos,
                       const float* __restrict__ wroot, const float* __restrict__ wrel) {
    int tid = threadIdx.x;
    int warp = tid >> 5, lane = tid & 31;
    int v = blockIdx.x * 8 + warp;
    if (v >= NN) return;
    double ar = 0.0, rr = 0.0;
    for (int d = lane; d < 128; d += 32) {
        double val = (d < FD) ? (double)x[(size_t)v * FD + d]
                              : (double)pos[(size_t)v * PD + (d - FD)];
        ar += val * (double)wroot[d];
        rr += val * (double)wrel[d];
    }
    for (int o = 16; o > 0; o >>= 1) {
        ar += __shfl_down_sync(0xffffffffu, ar, o);
        rr += __shfl_down_sync(0xffffffffu, rr, o);
    }
    if (lane == 0) {
        g_sroot[v] = ar;
        g_srel[v]  = rr;
        g_qrel[v]  = llrint(rr * QSCALE);
    }
}

// ---------------- edge pass ----------------
__global__ void k_edge1(const int* __restrict__ ei) {
    int e = blockIdx.x * blockDim.x + threadIdx.x;
    if (e >= EE) return;
    int s = ei[e], d = ei[EE + e];
    if (s == d) {
        atomicAdd(&g_selfcnt, 1);
    } else {
        atomicAdd(&g_deg[s], 1);
        atomicAdd(&g_relfix[d], (ull)g_qrel[s]);
    }
}

__global__ void k_minred() {
    int v = blockIdx.x * blockDim.x + threadIdx.x;
    if (v < NN) atomicMin(&g_degmin, g_deg[v]);
}

__global__ void k_kcalc() {
    long long kept = (long long)EE - g_selfcnt;
    double mean = (double)(kept + NN) / (double)NN;
    double b = log(mean - (double)g_degmin);
    double a = log(1.0 / 0.8);
    long long kk = (long long)ceil(a / b);
    int d = (int)kk + 2;
    if (d < 1) d = 1;
    if (d > 16) d = 16;
    g_depth = d;
}

// ---------------- score -> sortable key ----------------
__global__ void k_key(const float* __restrict__ bptr) {
    int i = blockIdx.x * blockDim.x + threadIdx.x;
    if (i >= MSEL) return;
    if (i < NN) {
        double sc = g_sroot[i] + g_srel[i] + (double)(long long)g_relfix[i] * QINV
                  + (double)bptr[0];
        float f = (float)sc;
        unsigned u = __float_as_uint(f);
        u = (u >> 31) ? ~u : (u | 0x80000000u);
        unsigned du = ~u;
        g_key[i] = ((ull)du << 32) | (unsigned)i;
    } else {
        g_key[i] = ~0ull;
    }
}

// ---------------- bitonic sort: global stage + smem-fused stages ----------------
__global__ void k_bitonic(int j, int k2) {
    int i = blockIdx.x * blockDim.x + threadIdx.x;
    int ixj = i ^ j;
    if (ixj > i) {
        ull a = g_key[i], b = g_key[ixj];
        bool up = ((i & k2) == 0);
        if ((a > b) == up) { g_key[i] = b; g_key[ixj] = a; }
    }
}

__global__ void __launch_bounds__(1024) k_sort_local() {
    __shared__ ull sh[2048];
    int base = blockIdx.x * 2048, t = threadIdx.x;
    sh[t] = g_key[base + t];
    sh[t + 1024] = g_key[base + t + 1024];
    __syncthreads();
    for (int k2 = 2; k2 <= 2048; k2 <<= 1) {
        for (int j = k2 >> 1; j > 0; j >>= 1) {
            #pragma unroll
            for (int q = 0; q < 2; q++) {
                int i = t + q * 1024;
                int ixj = i ^ j;
                if (ixj > i) {
                    bool up = (((base + i) & k2) == 0);
                    ull a = sh[i], b = sh[ixj];
                    if ((a > b) == up) { sh[i] = b; sh[ixj] = a; }
                }
            }
            __syncthreads();
        }
    }
    g_key[base + t] = sh[t];
    g_key[base + t + 1024] = sh[t + 1024];
}

__global__ void __launch_bounds__(1024) k_merge_local(int k2) {
    __shared__ ull sh[2048];
    int base = blockIdx.x * 2048, t = threadIdx.x;
    sh[t] = g_key[base + t];
    sh[t + 1024] = g_key[base + t + 1024];
    __syncthreads();
    for (int j = 1024; j > 0; j >>= 1) {
        #pragma unroll
        for (int q = 0; q < 2; q++) {
            int i = t + q * 1024;
            int ixj = i ^ j;
            if (ixj > i) {
                bool up = (((base + i) & k2) == 0);
                ull a = sh[i], b = sh[ixj];
                if ((a > b) == up) { sh[i] = b; sh[ixj] = a; }
            }
        }
        __syncthreads();
    }
    g_key[base + t] = sh[t];
    g_key[base + t + 1024] = sh[t + 1024];
}

// ---------------- scan A: deg -> indptr ----------------
__global__ void k_scanA1() {
    __shared__ int sh[1024];
    int b = blockIdx.x, tid = threadIdx.x;
    int idx = b * 1024 + tid;
    int v = (idx < NN) ? g_deg[idx] : 0;
    sh[tid] = v;
    __syncthreads();
    for (int d = 1; d < 1024; d <<= 1) {
        int t = (tid >= d) ? sh[tid - d] : 0;
        __syncthreads();
        sh[tid] += t;
        __syncthreads();
    }
    if (idx < NN) g_indptr[idx + 1] = sh[tid];
    if (tid == 1023) g_aux[b] = sh[1023];
}
__global__ void k_scanA2() {
    int run = 0;
    for (int b = 0; b < 98; b++) { int t = g_aux[b]; g_aux[b] = run; run += t; }
    g_indptr[0] = 0;
}
__global__ void k_scanA3() {
    int idx = blockIdx.x * 1024 + threadIdx.x;
    if (idx < NN) g_indptr[idx + 1] += g_aux[idx >> 10];
}

__global__ void k_fillself() {
    int v = blockIdx.x * 1024 + threadIdx.x;
    if (v < NN) {
        int p = g_indptr[v];
        g_adj[p] = v;          // self-loop at slot 0
        g_fill[v] = p + 1;
    }
}
__global__ void k_adjE(const int* __restrict__ ei) {
    int e = blockIdx.x * blockDim.x + threadIdx.x;
    if (e >= EE) return;
    int s = ei[e], d = ei[EE + e];
    if (s != d) g_adj[atomicAdd(&g_fill[s], 1)] = d;
}

// -------- grid barrier (all NBLK blocks resident; volatile poll + backoff) --------
__device__ __forceinline__ void gridbar(int* sgen) {
    __syncthreads();
    if (threadIdx.x == 0) {
        int g = *sgen;
        __threadfence();
        if (atomicAdd(&g_barArrive, 1) == NBLK - 1) {
            atomicExch(&g_barArrive, 0);
            __threadfence();
            atomicAdd(&g_barGen, 1);
        } else {
            while (((volatile int*)&g_barGen)[0] < g + 1) __nanosleep(64);
        }
        __threadfence();
        *sgen = g + 1;
    }
    __syncthreads();
}

// ------- speculative peel v9: redundant local compaction, 2 bars/round -------
__global__ void __launch_bounds__(256) k_peel9() {
    __shared__ int s_gen, s_abort, s_hi, s_stop, s_ncommit, s_lastp, s_qn;
    __shared__ int s_q[BB];            // block-local candidate queue (persistent)
    __shared__ int s_pref[256];
    __shared__ int s_tmp[BB];
    __shared__ int s_ms[BB];
    __shared__ int s_flag[BB];
    __shared__ unsigned s_B[BB * 4];
    __shared__ int s_cls[BB];
    __shared__ int s_rank[BB];
    int tid = threadIdx.x;
    int blk = blockIdx.x;
    if (tid == 0) { s_gen = g_barGen; s_qn = 0; }
    __syncthreads();
    int depth = g_depth;

    for (int round = 0; round < NN; round++) {
        int par = round & 1;
        unsigned epoch = (unsigned)(round + 1);
        // clear next round's HARD flag buffer + own soft-block mask.
        // (conf[par^1] last read before previous commit-end bar; blkm[blk] is
        //  written only by this block, after this clear in program order)
        if (tid == 0) g_conf[par ^ 1][blk] = 0;
        if (tid < 4) g_blkm[blk * 4 + tid] = 0u;

        // ---- redundant local compaction: deterministic fn of (s_q, g_cluster) ----
        {
            int qn = s_qn;
            int al = 0, cnd = 0;
            if (tid < qn) {
                cnd = s_q[tid];
                al = (g_cluster[cnd] == -1) ? 1 : 0;
            }
            s_pref[tid] = al;
            __syncthreads();
            for (int d = 1; d < 256; d <<= 1) {
                int v = (tid >= d) ? s_pref[tid - d] : 0;
                __syncthreads();
                s_pref[tid] += v;
                __syncthreads();
            }
            if (al) s_tmp[s_pref[tid] - 1] = cnd;
            __syncthreads();
            int w = s_pref[255];
            if (tid < w) s_q[tid] = s_tmp[tid];
            if (tid == 0) s_qn = w;
            __syncthreads();
        }

        // ---- lazy top-up (rare): all blocks agree via identical computation ----
        int needtop = (s_qn < QTH && g_scanbase < NN) ? 1 : 0;
        while (needtop) {
            int scanb = g_scanbase;
            int tg = blk * 256 + tid;
            int pos = scanb + tg;
            int fl = 0;
            if (pos < NN) {
                int s = (int)(g_key[pos] & 0xffffffffu);
                if (g_cluster[s] == -1) fl = 1;
            }
            g_aflag[tg] = fl;
            gridbar(&s_gen);                                   // scan bar a
            if (blk == 0) {
                int qn = s_qn;
                int need = BB - qn;
                const int FPT = NT / 256;                      // 128 flags/thread
                int base = tid * FPT;
                int cnt = 0;
                for (int k2 = 0; k2 < FPT; k2++) cnt += g_aflag[base + k2];
                s_pref[tid] = cnt;
                __syncthreads();
                for (int d = 1; d < 256; d <<= 1) {
                    int v = (tid >= d) ? s_pref[tid - d] : 0;
                    __syncthreads();
                    s_pref[tid] += v;
                    __syncthreads();
                }
                int excl = s_pref[tid] - cnt;
                int total = s_pref[255];
                int add = total < need ? total : need;
                int r = excl;
                for (int k2 = 0; k2 < FPT; k2++) {
                    if (g_aflag[base + k2]) {
                        int p2 = scanb + base + k2;
                        if (r < need) {
                            int nd = (int)(g_key[p2] & 0xffffffffu);
                            s_q[qn + r] = nd;
                            g_cand[qn + r] = nd;       // transfer to other blocks
                        }
                        if (r == add - 1) s_lastp = p2;
                        r++;
                    }
                }
                __syncthreads();
                if (tid == 0) {
                    int nq = qn + add;
                    int nsb = (total >= need && add > 0) ? (s_lastp + 1) : (scanb + NT);
                    g_qn = nq;
                    g_scanbase = nsb;
                    g_needtop = (nq < BB && nsb < NN) ? 1 : 0;
                    s_qn = nq;
                }
            }
            gridbar(&s_gen);                                   // scan bar b
            if (blk != 0) {
                int nq = g_qn;
                for (int i = s_qn + tid; i < nq; i += 256) s_q[i] = g_cand[i];
                __syncthreads();
                if (tid == 0) s_qn = nq;
            }
            __syncthreads();
            needtop = g_needtop;
        }

        int found = s_qn;
        if (found == 0) break;

        // ---- speculative BFS: one block per slot (v5 logic, local queue) ----
        if (blk < found) {
            int slot = blk;
            int* reg = (slot == 0) ? g_f0 : g_reg[slot];
            int cap  = (slot == 0) ? NN : REGC;
            int center = s_q[slot];
            unsigned mykey = (epoch << 10) | (unsigned)(1023 - slot);
            if (tid == 0) {
                s_abort = 0; s_hi = 0;
                unsigned old = atomicMax(&g_mark[center], mykey);
                if ((old >> 10) == epoch) {
                    int os = 1023 - (int)(old & 1023u);
                    if (os < slot) {
                        atomicOr(&g_blkm[slot * 4 + (os >> 5)], 1u << (os & 31));
                        s_abort = 1;
                    } else if (os > slot) {
                        atomicExch(&g_conf[par][os], 1);
                    }
                }
                if (!s_abort) { reg[0] = center; s_hi = 1; }
            }
            __syncthreads();
            int lo = 0;
            for (int lev = 0; lev < depth; lev++) {
                if (s_abort) break;
                int hi = s_hi;
                if (hi == lo) break;
                if (tid == 0 && atomicAdd(&g_conf[par][slot], 0)) s_abort = 1;
                __syncthreads();
                if (s_abort) break;
                for (int i = lo + tid; i < hi; i += 256) {
                    int u = reg[i];
                    int e0 = g_indptr[u] + 1, e1 = g_indptr[u + 1];  // skip self slot
                    for (int e = e0; e < e1; e++) {
                        int w = g_adj[e];
                        if (g_cluster[w] != -1) continue;
                        unsigned old = atomicMax(&g_mark[w], mykey);
                        bool own;
                        if ((old >> 10) != epoch) own = true;
                        else {
                            int os = 1023 - (int)(old & 1023u);
                            if (os == slot) continue;
                            if (os < slot) {
                                atomicOr(&g_blkm[slot * 4 + (os >> 5)], 1u << (os & 31));
                                continue;
                            }
                            atomicExch(&g_conf[par][os], 1); own = true;
                        }
                        if (own) {
                            int j = atomicAdd(&s_hi, 1);
                            if (j < cap) reg[j] = w;
                            else { atomicExch(&g_conf[par][slot], 1); s_abort = 1; }
                        }
                    }
                }
                __syncthreads();
                lo = hi;
            }
            if (tid == 0) g_regsz[slot] = s_hi < cap ? s_hi : cap;
        }
        gridbar(&s_gen);                                       // bar 1 (BFS end)

        // ---- commit analysis (v5): prefetch, serial walk, dead-skip ----
        for (int s = tid; s < found; s += 256) {
            unsigned m = g_mark[s_q[s]];
            int ms = -1;
            if ((m >> 10) == epoch) ms = 1023 - (int)(m & 1023u);
            s_ms[s] = ms;
            s_flag[s] = g_conf[par][s];
        }
        for (int i = tid; i < found * 4; i += 256) s_B[i] = g_blkm[i];
        __syncthreads();
        if (tid == 0) {
            unsigned ex0 = 0, ex1 = 0, ex2 = 0, ex3 = 0;
            int stop = found, r = 0;
            for (int s = 0; s < found; s++) {
                int ms = s_ms[s];
                bool ok = false;
                if (ms == s && !s_flag[s]) {
                    ok = ((s_B[4*s+0] & ~ex0) == 0) && ((s_B[4*s+1] & ~ex1) == 0)
                      && ((s_B[4*s+2] & ~ex2) == 0) && ((s_B[4*s+3] & ~ex3) == 0);
                }
                if (ok) {
                    s_cls[s] = 1; s_rank[s] = r; r++;
                    if      (s < 32)  ex0 |= 1u << s;
                    else if (s < 64)  ex1 |= 1u << (s - 32);
                    else if (s < 96)  ex2 |= 1u << (s - 64);
                    else              ex3 |= 1u << (s - 96);
                } else if (ms >= 0 && ms < s &&
                           (((ms < 32 ? ex0 : ms < 64 ? ex1 : ms < 96 ? ex2 : ex3)
                             >> (ms & 31)) & 1u)) {
                    s_cls[s] = 0;                 // dead: center inside exact region
                } else {
                    stop = s; break;              // unknown -> stop
                }
            }
            s_stop = stop; s_ncommit = r;
        }
        __syncthreads();
        int stop = s_stop;                        // >= 1 (slot 0 always exact)
        int C = g_C;

        // committed slots write their regions with re-ranked ids
        if (blk < stop && s_cls[blk] == 1) {
            int* reg = (blk == 0) ? g_f0 : g_reg[blk];
            int sz = g_regsz[blk];
            int cid = C + s_rank[blk];
            for (int i = tid; i < sz; i += 256) g_cluster[reg[i]] = cid;
        }
        if (blk == 0) {
            for (int s = tid; s < stop; s += 256)
                if (s_cls[s] == 1) g_centers[C + s_rank[s]] = s_q[s];
            if (tid == 0) g_C = C + s_ncommit;
        }
        gridbar(&s_gen);                                       // bar 2 (commit end)
    }
    if (blk == 0 && tid == 0) g_c = g_C;
}

// ---------------- concat reconstruction: key = (cluster<<32 | node) ----------------
__global__ void k_key2() {
    int i = blockIdx.x * blockDim.x + threadIdx.x;
    if (i >= MSEL) return;
    if (i < NN) {
        int cl = g_cluster[i];
        unsigned uc = (cl < 0) ? 0x7fffffffu : (unsigned)cl;
        g_key[i] = ((ull)uc << 32) | (unsigned)i;
    } else {
        g_key[i] = ~0ull;
    }
}

// After sort: position p holds key[p] = (cid[p]<<32 | oid[p]).
// Reference: clusters_buggy[v] = cid[ oid[v] ]  (cluster-id AT POSITION oid[v]).
__global__ void k_buggy() {
    int v = blockIdx.x * blockDim.x + threadIdx.x;
    if (v >= NN) return;
    int p = (int)(g_key[v] & 0xffffffffu);   // oid[v]
    int cid = 0;
    if (p >= 0 && p < NN) cid = (int)(g_key[p] >> 32);
    g_buggy[v] = cid;
}

// ---------------- edge dedup bitmap ----------------
__global__ void k_clearbmp() {
    int c = g_c; if (c > CMAXB) c = CMAXB;
    long long cw = (c + 63) >> 6;
    long long nw = (long long)c * cw;
    if (nw > (long long)BMPW) nw = BMPW;
    long long stride = (long long)gridDim.x * blockDim.x;
    for (long long i = blockIdx.x * (long long)blockDim.x + threadIdx.x; i < nw; i += stride)
        g_bmp[i] = 0ull;
}
__global__ void k_mark(const int* __restrict__ ei) {
    int e = blockIdx.x * blockDim.x + threadIdx.x;
    if (e >= EE) return;
    int s = ei[e], d = ei[EE + e];
    if (s == d) return;
    int a = g_buggy[s], b = g_buggy[d];
    if (a == b) return;
    int c = g_c;
    if (c > CMAXB) return;
    long long cw = (c + 63) >> 6;
    if (a < 0 || a >= c || b < 0 || b >= c) return;
    long long bit = (long long)a * (cw << 6) + b;
    atomicOr(&g_bmp[bit >> 6], 1ull << (bit & 63));
}
__global__ void k_rowcnt() {
    int a = blockIdx.x * blockDim.x + threadIdx.x;
    int c = g_c;
    if (a >= NN) return;
    if (a >= c || c > CMAXB) { g_rowcnt[a] = 0; return; }
    long long cw = (c + 63) >> 6;
    int cnt = 0;
    for (long long w = 0; w < cw; w++) cnt += __popcll(g_bmp[(long long)a * cw + w]);
    g_rowcnt[a] = cnt;
}

// ---------------- scan B ----------------
__global__ void k_scanB1() {
    __shared__ int sh[1024];
    int n = g_c; if (n > NN) n = NN;
    int b = blockIdx.x, tid = threadIdx.x;
    int idx = b * 1024 + tid;
    int v = (idx < n) ? g_rowcnt[idx] : 0;
    sh[tid] = v;
    __syncthreads();
    for (int d = 1; d < 1024; d <<= 1) {
        int t = (tid >= d) ? sh[tid - d] : 0;
        __syncthreads();
        sh[tid] += t;
        __syncthreads();
    }
    if (idx < n) g_rowincl[idx] = sh[tid];
    if (tid == 1023) g_aux[b] = sh[1023];
}
__global__ void k_scanB2() {
    int run = 0;
    for (int b = 0; b < 98; b++) { int t = g_aux[b]; g_aux[b] = run; run += t; }
}
__global__ void k_scanB3() {
    int n = g_c; if (n > NN) n = NN;
    int idx = blockIdx.x * 1024 + threadIdx.x;
    if (idx < n) g_rowincl[idx] += g_aux[idx >> 10];
}
__global__ void k_setE() {
    int c = g_c;
    g_Etot = (c > 0 && c <= NN) ? g_rowincl[c - 1] : 0;
}

// ---------------- x_p = segment_max ----------------
__global__ void k_xclear() {
    long long i = blockIdx.x * (long long)blockDim.x + threadIdx.x;
    if (i < (long long)NN * FD) g_enc[i] = 0u;
}
__global__ void k_xmax(const float* __restrict__ x) {
    long long i = blockIdx.x * (long long)blockDim.x + threadIdx.x;
    if (i >= (long long)NN * FD) return;
    int v = (int)(i / FD), f = (int)(i % FD);
    int cl = g_cluster[v];
    if (cl < 0 || cl >= NN) return;
    unsigned u = __float_as_uint(x[i]);
    u = (u >> 31) ? ~u : (u | 0x80000000u);
    atomicMax(&g_enc[(long long)cl * FD + f], u);
}
__global__ void k_xout(float* __restrict__ out, long long osz) {
    long long i = blockIdx.x * (long long)blockDim.x + threadIdx.x;
    if (i >= (long long)g_c * FD || i >= osz) return;
    unsigned u = g_enc[i];
    unsigned bits = (u & 0x80000000u) ? (u ^ 0x80000000u) : ~u;
    out[i] = __uint_as_float(bits);
}

// ---------------- new_ei emission ----------------
__global__ void k_emit(float* __restrict__ out, long long osz) {
    int a = blockIdx.x * blockDim.x + threadIdx.x;
    int c = g_c;
    if (a >= c || c > CMAXB) return;
    long long cw = (c + 63) >> 6;
    int base = g_rowincl[a] - g_rowcnt[a];
    long long eoff = (long long)FD * c;
    int Et = g_Etot;
    int cnt = 0;
    for (long long w = 0; w < cw; w++) {
        ull u = g_bmp[(long long)a * cw + w];
        while (u) {
            int bpos = __ffsll((long long)u) - 1;
            int b = (int)(w * 64 + bpos);
            long long p0 = eoff + base + cnt;
            long long p1 = eoff + Et + base + cnt;
            if (p0 >= 0 && p0 < osz) out[p0] = (float)a;
            if (p1 >= 0 && p1 < osz) out[p1] = (float)b;
            cnt++;
            u &= (u - 1);
        }
    }
}

// ---------------- pos_p ----------------
__global__ void k_posout(const float* __restrict__ pos, float* __restrict__ out,
                         long long osz) {
    int i = blockIdx.x * blockDim.x + threadIdx.x;
    int c = g_c;
    if (i >= 3 * c) return;
    int j = i / 3, d = i % 3;
    int ctr = g_centers[j];
    if (ctr < 0 || ctr >= NN) return;
    long long off = (long long)FD * c + 2LL * g_Etot + i;
    if (off >= 0 && off < osz)
        out[off] = pos[(long long)ctr * 3 + d];
}

// ---------------- host-side sort driver (launches only) ----------------
static void run_sort() {
    k_sort_local<<<MSEL / 2048, 1024>>>();
    for (int k2 = 4096; k2 <= MSEL; k2 <<= 1) {
        for (int j = k2 >> 1; j >= 2048; j >>= 1)
            k_bitonic<<<MSEL / 256, 256>>>(j, k2);
        k_merge_local<<<MSEL / 2048, 1024>>>(k2);
    }
}

// ---------------- launch ----------------
extern "C" void kernel_launch(void* const* d_in, const int* in_sizes, int n_in,
                              void* d_out, int out_size) {
    const float* x     = (const float*)d_in[0];
    const int*   ei    = (const int*)d_in[1];
    const float* pos   = (const float*)d_in[2];
    const float* wroot = (const float*)d_in[3];
    const float* wrel  = (const float*)d_in[4];
    const float* bb    = (const float*)d_in[5];
    float* out = (float*)d_out;
    long long osz = (long long)out_size;

    k_init<<<(NN + 255) / 256, 256>>>();
    k_dots<<<(NN + 7) / 8, 256>>>(x, pos, wroot, wrel);
    k_edge1<<<(EE + 255) / 256, 256>>>(ei);
    k_minred<<<(NN + 255) / 256, 256>>>();
    k_kcalc<<<1, 1>>>();
    k_key<<<MSEL / 256, 256>>>(bb);
    run_sort();                                   // sel order
    k_scanA1<<<98, 1024>>>();
    k_scanA2<<<1, 1>>>();
    k_scanA3<<<98, 1024>>>();
    k_fillself<<<98, 1024>>>();
    k_adjE<<<(EE + 255) / 256, 256>>>(ei);
    k_peel9<<<NBLK, 256>>>();
    k_key2<<<MSEL / 256, 256>>>();
    run_sort();                                   // concat order (cluster, node)
    k_clearbmp<<<2048, 256>>>();
    k_buggy<<<(NN + 255) / 256, 256>>>();
    k_mark<<<(EE + 255) / 256, 256>>>(ei);
    k_rowcnt<<<(NN + 255) / 256, 256>>>();
    k_scanB1<<<98, 1024>>>();
    k_scanB2<<<1, 1>>>();
    k_scanB3<<<98, 1024>>>();
    k_setE<<<1, 1>>>();
    k_xclear<<<(NN * FD + 255) / 256, 256>>>();
    k_xmax<<<(NN * FD + 255) / 256, 256>>>(x);
    k_xout<<<(NN * FD + 255) / 256, 256>>>(out, osz);
    k_emit<<<(NN + 255) / 256, 256>>>(out, osz);
    k_posout<<<(3 * NN + 255) / 256, 256>>>(pos, out, osz);
}

// round 17
// speedup vs baseline: 1.7175x; 1.0072x over previous
#include <cuda_runtime.h>
#include <math.h>
#include <stdint.h>

typedef unsigned long long ull;

// ---------------- problem constants ----------------
#define NN 100000
#define EE 1600000
#define FD 125
#define PD 3
#define MSEL 131072            // pow2 >= NN
#define NBLK 128               // persistent blocks (all wave-1 resident)
#define NT (NBLK*256)          // grid threads = 32768
#define BB 128                 // max speculative batch = NBLK
#define QTH 64                 // top-up threshold: scan only when queue < QTH
#define REGC 16384             // per-slot region capacity (slots > 0)
#define SFR 2048               // smem frontier mirror size
#define SENT 0xFFFFFFFFu       // claimed-node sentinel mark
#define BMPW (1u<<24)          // 2^24 words = 2^30 bits bitmap (c <= 32768)
#define CMAXB 32768
#define QSCALE 17179869184.0   // 2^34 fixed-point scale
#define QINV   (1.0/17179869184.0)

// ---------------- static device scratch ----------------
__device__ double  g_sroot[NN];
__device__ double  g_srel[NN];
__device__ long long g_qrel[NN];
__device__ ull     g_relfix[NN];
__device__ int     g_deg[NN];
__device__ int     g_indptr[NN + 1];
__device__ int     g_fill[NN];
__device__ int     g_adj[NN + EE];
__device__ ull     g_key[MSEL];
__device__ int     g_cluster[NN];
__device__ int     g_centers[NN];
__device__ int     g_buggy[NN];
__device__ int     g_f0[NN];           // slot-0 region list (never truncates)
__device__ int     g_reg[BB][REGC];    // per-slot region lists (slots 1..BB-1)
__device__ int     g_regsz[BB];
__device__ unsigned g_mark[NN];        // (epoch<<10)|(1023-slot); SENT = claimed
__device__ int     g_cand[BB];         // top-up transfer buffer only
__device__ int     g_conf[2][BB];      // HARD flags, double-buffered by round parity
__device__ unsigned g_blkm[BB * 4];    // blocked-by bitmask (lost-at-touch), per slot
__device__ int     g_aflag[NT];
__device__ unsigned int g_enc[NN * FD];
__device__ ull     g_bmp[BMPW];        // 128MB
__device__ int     g_rowcnt[NN];
__device__ int     g_rowincl[NN];
__device__ int     g_aux[128];
__device__ int     g_selfcnt;
__device__ int     g_degmin;
__device__ int     g_depth;
__device__ int     g_c;
__device__ int     g_Etot;
// persistent-kernel coordination
__device__ int     g_C, g_qn, g_needtop, g_scanbase;
__device__ int     g_barArrive, g_barGen;

// ---------------- init ----------------
__global__ void k_init() {
    int v = blockIdx.x * blockDim.x + threadIdx.x;
    if (v < NN) {
        g_deg[v] = 1;        // appended self-loop
        g_relfix[v] = 0ull;
        g_cluster[v] = -1;
        g_mark[v] = 0u;
    }
    if (v < BB) { g_conf[0][v] = 0; g_conf[1][v] = 0; g_regsz[v] = 0; }
    if (v < BB * 4) g_blkm[v] = 0u;
    if (v == 0) {
        g_selfcnt = 0; g_degmin = 0x7fffffff;
        g_C = 0;
        g_qn = 0; g_needtop = 1; g_scanbase = 0;
        g_barArrive = 0; g_barGen = 0;
    }
}

// ---------------- per-node 128-dim dots (fp64, warp per node) ----------------
__global__ void k_dots(const float* __restrict__ x, const float* __restrict__ pos,
                       const float* __restrict__ wroot, const float* __restrict__ wrel) {
    int tid = threadIdx.x;
    int warp = tid >> 5, lane = tid & 31;
    int v = blockIdx.x * 8 + warp;
    if (v >= NN) return;
    double ar = 0.0, rr = 0.0;
    for (int d = lane; d < 128; d += 32) {
        double val = (d < FD) ? (double)x[(size_t)v * FD + d]
                              : (double)pos[(size_t)v * PD + (d - FD)];
        ar += val * (double)wroot[d];
        rr += val * (double)wrel[d];
    }
    for (int o = 16; o > 0; o >>= 1) {
        ar += __shfl_down_sync(0xffffffffu, ar, o);
        rr += __shfl_down_sync(0xffffffffu, rr, o);
    }
    if (lane == 0) {
        g_sroot[v] = ar;
        g_srel[v]  = rr;
        g_qrel[v]  = llrint(rr * QSCALE);
    }
}

// ---------------- edge pass ----------------
__global__ void k_edge1(const int* __restrict__ ei) {
    int e = blockIdx.x * blockDim.x + threadIdx.x;
    if (e >= EE) return;
    int s = ei[e], d = ei[EE + e];
    if (s == d) {
        atomicAdd(&g_selfcnt, 1);
    } else {
        atomicAdd(&g_deg[s], 1);
        atomicAdd(&g_relfix[d], (ull)g_qrel[s]);
    }
}

__global__ void k_minred() {
    int v = blockIdx.x * blockDim.x + threadIdx.x;
    if (v < NN) atomicMin(&g_degmin, g_deg[v]);
}

__global__ void k_kcalc() {
    long long kept = (long long)EE - g_selfcnt;
    double mean = (double)(kept + NN) / (double)NN;
    double b = log(mean - (double)g_degmin);
    double a = log(1.0 / 0.8);
    long long kk = (long long)ceil(a / b);
    int d = (int)kk + 2;
    if (d < 1) d = 1;
    if (d > 16) d = 16;
    g_depth = d;
}

// ---------------- score -> sortable key ----------------
__global__ void k_key(const float* __restrict__ bptr) {
    int i = blockIdx.x * blockDim.x + threadIdx.x;
    if (i >= MSEL) return;
    if (i < NN) {
        double sc = g_sroot[i] + g_srel[i] + (double)(long long)g_relfix[i] * QINV
                  + (double)bptr[0];
        float f = (float)sc;
        unsigned u = __float_as_uint(f);
        u = (u >> 31) ? ~u : (u | 0x80000000u);
        unsigned du = ~u;
        g_key[i] = ((ull)du << 32) | (unsigned)i;
    } else {
        g_key[i] = ~0ull;
    }
}

// ---------------- bitonic sort: global stage + smem-fused stages ----------------
__global__ void k_bitonic(int j, int k2) {
    int i = blockIdx.x * blockDim.x + threadIdx.x;
    int ixj = i ^ j;
    if (ixj > i) {
        ull a = g_key[i], b = g_key[ixj];
        bool up = ((i & k2) == 0);
        if ((a > b) == up) { g_key[i] = b; g_key[ixj] = a; }
    }
}

__global__ void __launch_bounds__(1024) k_sort_local() {
    __shared__ ull sh[2048];
    int base = blockIdx.x * 2048, t = threadIdx.x;
    sh[t] = g_key[base + t];
    sh[t + 1024] = g_key[base + t + 1024];
    __syncthreads();
    for (int k2 = 2; k2 <= 2048; k2 <<= 1) {
        for (int j = k2 >> 1; j > 0; j >>= 1) {
            #pragma unroll
            for (int q = 0; q < 2; q++) {
                int i = t + q * 1024;
                int ixj = i ^ j;
                if (ixj > i) {
                    bool up = (((base + i) & k2) == 0);
                    ull a = sh[i], b = sh[ixj];
                    if ((a > b) == up) { sh[i] = b; sh[ixj] = a; }
                }
            }
            __syncthreads();
        }
    }
    g_key[base + t] = sh[t];
    g_key[base + t + 1024] = sh[t + 1024];
}

__global__ void __launch_bounds__(1024) k_merge_local(int k2) {
    __shared__ ull sh[2048];
    int base = blockIdx.x * 2048, t = threadIdx.x;
    sh[t] = g_key[base + t];
    sh[t + 1024] = g_key[base + t + 1024];
    __syncthreads();
    for (int j = 1024; j > 0; j >>= 1) {
        #pragma unroll
        for (int q = 0; q < 2; q++) {
            int i = t + q * 1024;
            int ixj = i ^ j;
            if (ixj > i) {
                bool up = (((base + i) & k2) == 0);
                ull a = sh[i], b = sh[ixj];
                if ((a > b) == up) { sh[i] = b; sh[ixj] = a; }
            }
        }
        __syncthreads();
    }
    g_key[base + t] = sh[t];
    g_key[base + t + 1024] = sh[t + 1024];
}

// ---------------- scan A: deg -> indptr ----------------
__global__ void k_scanA1() {
    __shared__ int sh[1024];
    int b = blockIdx.x, tid = threadIdx.x;
    int idx = b * 1024 + tid;
    int v = (idx < NN) ? g_deg[idx] : 0;
    sh[tid] = v;
    __syncthreads();
    for (int d = 1; d < 1024; d <<= 1) {
        int t = (tid >= d) ? sh[tid - d] : 0;
        __syncthreads();
        sh[tid] += t;
        __syncthreads();
    }
    if (idx < NN) g_indptr[idx + 1] = sh[tid];
    if (tid == 1023) g_aux[b] = sh[1023];
}
__global__ void k_scanA2() {
    int run = 0;
    for (int b = 0; b < 98; b++) { int t = g_aux[b]; g_aux[b] = run; run += t; }
    g_indptr[0] = 0;
}
__global__ void k_scanA3() {
    int idx = blockIdx.x * 1024 + threadIdx.x;
    if (idx < NN) g_indptr[idx + 1] += g_aux[idx >> 10];
}

__global__ void k_fillself() {
    int v = blockIdx.x * 1024 + threadIdx.x;
    if (v < NN) {
        int p = g_indptr[v];
        g_adj[p] = v;          // self-loop at slot 0
        g_fill[v] = p + 1;
    }
}
__global__ void k_adjE(const int* __restrict__ ei) {
    int e = blockIdx.x * blockDim.x + threadIdx.x;
    if (e >= EE) return;
    int s = ei[e], d = ei[EE + e];
    if (s != d) g_adj[atomicAdd(&g_fill[s], 1)] = d;
}

// -------- grid barrier (all NBLK blocks resident; volatile poll + backoff) --------
__device__ __forceinline__ void gridbar(int* sgen) {
    __syncthreads();
    if (threadIdx.x == 0) {
        int g = *sgen;
        __threadfence();
        if (atomicAdd(&g_barArrive, 1) == NBLK - 1) {
            atomicExch(&g_barArrive, 0);
            __threadfence();
            atomicAdd(&g_barGen, 1);
        } else {
            while (((volatile int*)&g_barGen)[0] < g + 1) __nanosleep(64);
        }
        __threadfence();
        *sgen = g + 1;
    }
    __syncthreads();
}

// ---- speculative peel v10: sentinel marks (no cluster read in BFS), smem frontier ----
__global__ void __launch_bounds__(256) k_peel10() {
    __shared__ int s_gen, s_abort, s_hi, s_stop, s_ncommit, s_lastp, s_qn;
    __shared__ int s_q[BB];            // block-local candidate queue (persistent)
    __shared__ int s_fr[SFR];          // frontier mirror
    __shared__ int s_pref[256];
    __shared__ int s_tmp[BB];
    __shared__ int s_ms[BB];
    __shared__ int s_flag[BB];
    __shared__ unsigned s_B[BB * 4];
    __shared__ int s_cls[BB];
    __shared__ int s_rank[BB];
    int tid = threadIdx.x;
    int blk = blockIdx.x;
    if (tid == 0) { s_gen = g_barGen; s_qn = 0; }
    __syncthreads();
    int depth = g_depth;

    for (int round = 0; round < NN; round++) {
        int par = round & 1;
        unsigned epoch = (unsigned)(round + 1);
        if (tid == 0) g_conf[par ^ 1][blk] = 0;
        if (tid < 4) g_blkm[blk * 4 + tid] = 0u;

        // ---- redundant local compaction (deterministic fn of (s_q, g_cluster)) ----
        {
            int qn = s_qn;
            int al = 0, cnd = 0;
            if (tid < qn) {
                cnd = s_q[tid];
                al = (g_cluster[cnd] == -1) ? 1 : 0;
            }
            s_pref[tid] = al;
            __syncthreads();
            for (int d = 1; d < 256; d <<= 1) {
                int v = (tid >= d) ? s_pref[tid - d] : 0;
                __syncthreads();
                s_pref[tid] += v;
                __syncthreads();
            }
            if (al) s_tmp[s_pref[tid] - 1] = cnd;
            __syncthreads();
            int w = s_pref[255];
            if (tid < w) s_q[tid] = s_tmp[tid];
            if (tid == 0) s_qn = w;
            __syncthreads();
        }

        // ---- lazy top-up (rare) ----
        int needtop = (s_qn < QTH && g_scanbase < NN) ? 1 : 0;
        while (needtop) {
            int scanb = g_scanbase;
            int tg = blk * 256 + tid;
            int pos = scanb + tg;
            int fl = 0;
            if (pos < NN) {
                int s = (int)(g_key[pos] & 0xffffffffu);
                if (g_cluster[s] == -1) fl = 1;
            }
            g_aflag[tg] = fl;
            gridbar(&s_gen);                                   // scan bar a
            if (blk == 0) {
                int qn = s_qn;
                int need = BB - qn;
                const int FPT = NT / 256;                      // 128 flags/thread
                int base = tid * FPT;
                int cnt = 0;
                for (int k2 = 0; k2 < FPT; k2++) cnt += g_aflag[base + k2];
                s_pref[tid] = cnt;
                __syncthreads();
                for (int d = 1; d < 256; d <<= 1) {
                    int v = (tid >= d) ? s_pref[tid - d] : 0;
                    __syncthreads();
                    s_pref[tid] += v;
                    __syncthreads();
                }
                int excl = s_pref[tid] - cnt;
                int total = s_pref[255];
                int add = total < need ? total : need;
                int r = excl;
                for (int k2 = 0; k2 < FPT; k2++) {
                    if (g_aflag[base + k2]) {
                        int p2 = scanb + base + k2;
                        if (r < need) {
                            int nd = (int)(g_key[p2] & 0xffffffffu);
                            s_q[qn + r] = nd;
                            g_cand[qn + r] = nd;       // transfer to other blocks
                        }
                        if (r == add - 1) s_lastp = p2;
                        r++;
                    }
                }
                __syncthreads();
                if (tid == 0) {
                    int nq = qn + add;
                    int nsb = (total >= need && add > 0) ? (s_lastp + 1) : (scanb + NT);
                    g_qn = nq;
                    g_scanbase = nsb;
                    g_needtop = (nq < BB && nsb < NN) ? 1 : 0;
                    s_qn = nq;
                }
            }
            gridbar(&s_gen);                                   // scan bar b
            if (blk != 0) {
                int nq = g_qn;
                for (int i = s_qn + tid; i < nq; i += 256) s_q[i] = g_cand[i];
                __syncthreads();
                if (tid == 0) s_qn = nq;
            }
            __syncthreads();
            needtop = g_needtop;
        }

        int found = s_qn;
        if (found == 0) break;

        // ---- speculative BFS: one block per slot; sentinel marks; smem frontier ----
        if (blk < found) {
            int slot = blk;
            int* reg = (slot == 0) ? g_f0 : g_reg[slot];
            int cap  = (slot == 0) ? NN : REGC;
            int center = s_q[slot];
            unsigned mykey = (epoch << 10) | (unsigned)(1023 - slot);
            if (tid == 0) {
                s_abort = 0; s_hi = 0;
                unsigned old = atomicMax(&g_mark[center], mykey);
                // center is alive (compaction) so old != SENT
                if ((old >> 10) == epoch) {
                    int os = 1023 - (int)(old & 1023u);
                    if (os < slot) {
                        atomicOr(&g_blkm[slot * 4 + (os >> 5)], 1u << (os & 31));
                        s_abort = 1;
                    } else if (os > slot) {
                        atomicExch(&g_conf[par][os], 1);
                    }
                }
                if (!s_abort) { reg[0] = center; s_fr[0] = center; s_hi = 1; }
            }
            __syncthreads();
            int lo = 0;
            for (int lev = 0; lev < depth; lev++) {
                if (s_abort) break;
                int hi = s_hi;
                if (hi == lo) break;
                if (tid == 0 && ((volatile int*)g_conf[par])[slot]) s_abort = 1;
                __syncthreads();
                if (s_abort) break;
                for (int i = lo + tid; i < hi; i += 256) {
                    int u = (i < SFR) ? s_fr[i] : reg[i];
                    int e0 = g_indptr[u] + 1, e1 = g_indptr[u + 1];  // skip self slot
                    for (int e = e0; e < e1; e++) {
                        int w = g_adj[e];
                        unsigned old = atomicMax(&g_mark[w], mykey);
                        if (old == SENT) continue;            // claimed node
                        bool own;
                        if ((old >> 10) != epoch) own = true;
                        else {
                            int os = 1023 - (int)(old & 1023u);
                            if (os == slot) continue;
                            if (os < slot) {
                                atomicOr(&g_blkm[slot * 4 + (os >> 5)], 1u << (os & 31));
                                continue;
                            }
                            atomicExch(&g_conf[par][os], 1); own = true;
                        }
                        if (own) {
                            int j = atomicAdd(&s_hi, 1);
                            if (j < cap) {
                                reg[j] = w;
                                if (j < SFR) s_fr[j] = w;
                            } else { atomicExch(&g_conf[par][slot], 1); s_abort = 1; }
                        }
                    }
                }
                __syncthreads();
                lo = hi;
            }
            if (tid == 0) g_regsz[slot] = s_hi < cap ? s_hi : cap;
        }
        gridbar(&s_gen);                                       // bar 1 (BFS end)

        // ---- commit analysis (v5 walk): prefetch, serial walk, dead-skip ----
        for (int s = tid; s < found; s += 256) {
            unsigned m = g_mark[s_q[s]];
            int ms = -1;
            if ((m >> 10) == epoch) ms = 1023 - (int)(m & 1023u);
            s_ms[s] = ms;
            s_flag[s] = g_conf[par][s];
        }
        for (int i = tid; i < found * 4; i += 256) s_B[i] = g_blkm[i];
        __syncthreads();
        if (tid == 0) {
            unsigned ex0 = 0, ex1 = 0, ex2 = 0, ex3 = 0;
            int stop = found, r = 0;
            for (int s = 0; s < found; s++) {
                int ms = s_ms[s];
                bool ok = false;
                if (ms == s && !s_flag[s]) {
                    ok = ((s_B[4*s+0] & ~ex0) == 0) && ((s_B[4*s+1] & ~ex1) == 0)
                      && ((s_B[4*s+2] & ~ex2) == 0) && ((s_B[4*s+3] & ~ex3) == 0);
                }
                if (ok) {
                    s_cls[s] = 1; s_rank[s] = r; r++;
                    if      (s < 32)  ex0 |= 1u << s;
                    else if (s < 64)  ex1 |= 1u << (s - 32);
                    else if (s < 96)  ex2 |= 1u << (s - 64);
                    else              ex3 |= 1u << (s - 96);
                } else if (ms >= 0 && ms < s &&
                           (((ms < 32 ? ex0 : ms < 64 ? ex1 : ms < 96 ? ex2 : ex3)
                             >> (ms & 31)) & 1u)) {
                    s_cls[s] = 0;                 // dead: center inside exact region
                } else {
                    stop = s; break;              // unknown -> stop
                }
            }
            s_stop = stop; s_ncommit = r;
        }
        __syncthreads();
        int stop = s_stop;                        // >= 1 (slot 0 always exact)
        int C = g_C;

        // committed slots write cluster ids AND sentinel marks
        if (blk < stop && s_cls[blk] == 1) {
            int* reg = (blk == 0) ? g_f0 : g_reg[blk];
            int sz = g_regsz[blk];
            int cid = C + s_rank[blk];
            for (int i = tid; i < sz; i += 256) {
                int w = reg[i];
                g_cluster[w] = cid;
                g_mark[w] = SENT;
            }
        }
        if (blk == 0) {
            for (int s = tid; s < stop; s += 256)
                if (s_cls[s] == 1) g_centers[C + s_rank[s]] = s_q[s];
            if (tid == 0) g_C = C + s_ncommit;
        }
        gridbar(&s_gen);                                       // bar 2 (commit end)
    }
    if (blk == 0 && tid == 0) g_c = g_C;
}

// ---------------- concat reconstruction: key = (cluster<<32 | node) ----------------
__global__ void k_key2() {
    int i = blockIdx.x * blockDim.x + threadIdx.x;
    if (i >= MSEL) return;
    if (i < NN) {
        int cl = g_cluster[i];
        unsigned uc = (cl < 0) ? 0x7fffffffu : (unsigned)cl;
        g_key[i] = ((ull)uc << 32) | (unsigned)i;
    } else {
        g_key[i] = ~0ull;
    }
}

// After sort: position p holds key[p] = (cid[p]<<32 | oid[p]).
// Reference: clusters_buggy[v] = cid[ oid[v] ].
__global__ void k_buggy() {
    int v = blockIdx.x * blockDim.x + threadIdx.x;
    if (v >= NN) return;
    int p = (int)(g_key[v] & 0xffffffffu);   // oid[v]
    int cid = 0;
    if (p >= 0 && p < NN) cid = (int)(g_key[p] >> 32);
    g_buggy[v] = cid;
}

// ---------------- edge dedup bitmap ----------------
__global__ void k_clearbmp() {
    int c = g_c; if (c > CMAXB) c = CMAXB;
    long long cw = (c + 63) >> 6;
    long long nw = (long long)c * cw;
    if (nw > (long long)BMPW) nw = BMPW;
    long long stride = (long long)gridDim.x * blockDim.x;
    for (long long i = blockIdx.x * (long long)blockDim.x + threadIdx.x; i < nw; i += stride)
        g_bmp[i] = 0ull;
}
__global__ void k_mark(const int* __restrict__ ei) {
    int e = blockIdx.x * blockDim.x + threadIdx.x;
    if (e >= EE) return;
    int s = ei[e], d = ei[EE + e];
    if (s == d) return;
    int a = g_buggy[s], b = g_buggy[d];
    if (a == b) return;
    int c = g_c;
    if (c > CMAXB) return;
    long long cw = (c + 63) >> 6;
    if (a < 0 || a >= c || b < 0 || b >= c) return;
    long long bit = (long long)a * (cw << 6) + b;
    atomicOr(&g_bmp[bit >> 6], 1ull << (bit & 63));
}
__global__ void k_rowcnt() {
    int a = blockIdx.x * blockDim.x + threadIdx.x;
    int c = g_c;
    if (a >= NN) return;
    if (a >= c || c > CMAXB) { g_rowcnt[a] = 0; return; }
    long long cw = (c + 63) >> 6;
    int cnt = 0;
    for (long long w = 0; w < cw; w++) cnt += __popcll(g_bmp[(long long)a * cw + w]);
    g_rowcnt[a] = cnt;
}

// ---------------- scan B ----------------
__global__ void k_scanB1() {
    __shared__ int sh[1024];
    int n = g_c; if (n > NN) n = NN;
    int b = blockIdx.x, tid = threadIdx.x;
    int idx = b * 1024 + tid;
    int v = (idx < n) ? g_rowcnt[idx] : 0;
    sh[tid] = v;
    __syncthreads();
    for (int d = 1; d < 1024; d <<= 1) {
        int t = (tid >= d) ? sh[tid - d] : 0;
        __syncthreads();
        sh[tid] += t;
        __syncthreads();
    }
    if (idx < n) g_rowincl[idx] = sh[tid];
    if (tid == 1023) g_aux[b] = sh[1023];
}
__global__ void k_scanB2() {
    int run = 0;
    for (int b = 0; b < 98; b++) { int t = g_aux[b]; g_aux[b] = run; run += t; }
}
__global__ void k_scanB3() {
    int n = g_c; if (n > NN) n = NN;
    int idx = blockIdx.x * 1024 + threadIdx.x;
    if (idx < n) g_rowincl[idx] += g_aux[idx >> 10];
}
__global__ void k_setE() {
    int c = g_c;
    g_Etot = (c > 0 && c <= NN) ? g_rowincl[c - 1] : 0;
}

// ---------------- x_p = segment_max ----------------
__global__ void k_xclear() {
    long long i = blockIdx.x * (long long)blockDim.x + threadIdx.x;
    if (i < (long long)NN * FD) g_enc[i] = 0u;
}
__global__ void k_xmax(const float* __restrict__ x) {
    long long i = blockIdx.x * (long long)blockDim.x + threadIdx.x;
    if (i >= (long long)NN * FD) return;
    int v = (int)(i / FD), f = (int)(i % FD);
    int cl = g_cluster[v];
    if (cl < 0 || cl >= NN) return;
    unsigned u = __float_as_uint(x[i]);
    u = (u >> 31) ? ~u : (u | 0x80000000u);
    atomicMax(&g_enc[(long long)cl * FD + f], u);
}
__global__ void k_xout(float* __restrict__ out, long long osz) {
    long long i = blockIdx.x * (long long)blockDim.x + threadIdx.x;
    if (i >= (long long)g_c * FD || i >= osz) return;
    unsigned u = g_enc[i];
    unsigned bits = (u & 0x80000000u) ? (u ^ 0x80000000u) : ~u;
    out[i] = __uint_as_float(bits);
}

// ---------------- new_ei emission ----------------
__global__ void k_emit(float* __restrict__ out, long long osz) {
    int a = blockIdx.x * blockDim.x + threadIdx.x;
    int c = g_c;
    if (a >= c || c > CMAXB) return;
    long long cw = (c + 63) >> 6;
    int base = g_rowincl[a] - g_rowcnt[a];
    long long eoff = (long long)FD * c;
    int Et = g_Etot;
    int cnt = 0;
    for (long long w = 0; w < cw; w++) {
        ull u = g_bmp[(long long)a * cw + w];
        while (u) {
            int bpos = __ffsll((long long)u) - 1;
            int b = (int)(w * 64 + bpos);
            long long p0 = eoff + base + cnt;
            long long p1 = eoff + Et + base + cnt;
            if (p0 >= 0 && p0 < osz) out[p0] = (float)a;
            if (p1 >= 0 && p1 < osz) out[p1] = (float)b;
            cnt++;
            u &= (u - 1);
        }
    }
}

// ---------------- pos_p ----------------
__global__ void k_posout(const float* __restrict__ pos, float* __restrict__ out,
                         long long osz) {
    int i = blockIdx.x * blockDim.x + threadIdx.x;
    int c = g_c;
    if (i >= 3 * c) return;
    int j = i / 3, d = i % 3;
    int ctr = g_centers[j];
    if (ctr < 0 || ctr >= NN) return;
    long long off = (long long)FD * c + 2LL * g_Etot + i;
    if (off >= 0 && off < osz)
        out[off] = pos[(long long)ctr * 3 + d];
}

// ---------------- host-side sort driver (launches only) ----------------
static void run_sort() {
    k_sort_local<<<MSEL / 2048, 1024>>>();
    for (int k2 = 4096; k2 <= MSEL; k2 <<= 1) {
        for (int j = k2 >> 1; j >= 2048; j >>= 1)
            k_bitonic<<<MSEL / 256, 256>>>(j, k2);
        k_merge_local<<<MSEL / 2048, 1024>>>(k2);
    }
}

// ---------------- launch ----------------
extern "C" void kernel_launch(void* const* d_in, const int* in_sizes, int n_in,
                              void* d_out, int out_size) {
    const float* x     = (const float*)d_in[0];
    const int*   ei    = (const int*)d_in[1];
    const float* pos   = (const float*)d_in[2];
    const float* wroot = (const float*)d_in[3];
    const float* wrel  = (const float*)d_in[4];
    const float* bb    = (const float*)d_in[5];
    float* out = (float*)d_out;
    long long osz = (long long)out_size;

    k_init<<<(NN + 255) / 256, 256>>>();
    k_dots<<<(NN + 7) / 8, 256>>>(x, pos, wroot, wrel);
    k_edge1<<<(EE + 255) / 256, 256>>>(ei);
    k_minred<<<(NN + 255) / 256, 256>>>();
    k_kcalc<<<1, 1>>>();
    k_key<<<MSEL / 256, 256>>>(bb);
    run_sort();                                   // sel order
    k_scanA1<<<98, 1024>>>();
    k_scanA2<<<1, 1>>>();
    k_scanA3<<<98, 1024>>>();
    k_fillself<<<98, 1024>>>();
    k_adjE<<<(EE + 255) / 256, 256>>>(ei);
    k_peel10<<<NBLK, 256>>>();
    k_key2<<<MSEL / 256, 256>>>();
    run_sort();                                   // concat order (cluster, node)
    k_clearbmp<<<2048, 256>>>();
    k_buggy<<<(NN + 255) / 256, 256>>>();
    k_mark<<<(EE + 255) / 256, 256>>>(ei);
    k_rowcnt<<<(NN + 255) / 256, 256>>>();
    k_scanB1<<<98, 1024>>>();
    k_scanB2<<<1, 1>>>();
    k_scanB3<<<98, 1024>>>();
    k_setE<<<1, 1>>>();
    k_xclear<<<(NN * FD + 255) / 256, 256>>>();
    k_xmax<<<(NN * FD + 255) / 256, 256>>>(x);
    k_xout<<<(NN * FD + 255) / 256, 256>>>(out, osz);
    k_emit<<<(NN + 255) / 256, 256>>>(out, osz);
    k_posout<<<(3 * NN + 255) / 256, 256>>>(pos, out, osz);
}